// round 1
// baseline (speedup 1.0000x reference)
#include <cuda_runtime.h>
#include <math.h>

// Problem constants (fixed by reference)
#define LNUM 4
#define NB   8
#define Bsz  16
#define Ssz  512
#define Dsz  512
#define Msz  (Bsz * Ssz)          // 8192 token rows
#define BSD  (Bsz * Ssz * Dsz)    // 4,194,304

// ---------------- device scratch (static; no allocation) ----------------
__device__ float g_c[BSD];                 // cortical state
__device__ float g_b[BSD];                 // brainstem state
__device__ float g_xn[BSD];                // LN output
__device__ float g_h1[Bsz * Ssz * 2 * Dsz];// GEMM1 output (up to 2D wide)
__device__ float g_mean_c[Bsz * Dsz];      // mean over seq
__device__ float g_mean_b[Bsz * Dsz];
__device__ int   g_top_c[2];
__device__ int   g_top_b[2];

// ---------------- column mean over seq: out[b,d] = mean_s x[b,s,d] ----------------
__global__ void colmean_kernel(const float* __restrict__ x, float* __restrict__ out) {
    int b = blockIdx.x;
    int d = blockIdx.y * 256 + threadIdx.x;
    const float* p = x + (size_t)b * Ssz * Dsz + d;
    float s = 0.f;
#pragma unroll 8
    for (int t = 0; t < Ssz; t++) s += p[(size_t)t * Dsz];
    out[b * Dsz + d] = s * (1.0f / Ssz);
}

// ---------------- routing: top-2 of sigmoid(mean0 @ wsel + bsel)*0.7 + 0.15 ----------------
__global__ void route_kernel(const float* __restrict__ mean0, const float* __restrict__ wsel,
                             const float* __restrict__ bsel, int* __restrict__ top) {
    int lane = threadIdx.x & 31, w = threadIdx.x >> 5;  // 8 warps, one per block score
    float s = 0.f;
    for (int d = lane; d < Dsz; d += 32) s += mean0[d] * wsel[d * NB + w];
#pragma unroll
    for (int o = 16; o > 0; o >>= 1) s += __shfl_down_sync(0xffffffffu, s, o);
    __shared__ float adj[NB];
    if (lane == 0) {
        float sc = 1.f / (1.f + expf(-(s + bsel[w])));
        adj[w] = sc * 0.7f + 0.15f;
    }
    __syncthreads();
    if (threadIdx.x == 0) {
        int i1 = 0; float v1 = adj[0];
        for (int n = 1; n < NB; n++) if (adj[n] > v1) { v1 = adj[n]; i1 = n; }
        int i2 = -1; float v2 = -1e30f;
        for (int n = 0; n < NB; n++) if (n != i1 && adj[n] > v2) { v2 = adj[n]; i2 = n; }
        top[0] = i1; top[1] = i2;
    }
}

// ---------------- LayerNorm with per-routed-block gamma/beta ----------------
__global__ void ln_kernel(const float* __restrict__ x, float* __restrict__ xn,
                          const float* __restrict__ lng, const float* __restrict__ lnb,
                          const int* __restrict__ top, int jsel) {
    int i = top[jsel];
    int row = blockIdx.x;
    const float* xr = x + (size_t)row * Dsz;
    int t = threadIdx.x;                    // 256 threads, 2 elems each
    float v0 = xr[t], v1 = xr[t + 256];
    __shared__ float red[256];
    red[t] = v0 + v1;
    __syncthreads();
    for (int o = 128; o > 0; o >>= 1) { if (t < o) red[t] += red[t + o]; __syncthreads(); }
    __shared__ float mu_s;
    if (t == 0) mu_s = red[0] * (1.f / Dsz);
    __syncthreads();
    float m = mu_s;
    float d0 = v0 - m, d1 = v1 - m;
    red[t] = d0 * d0 + d1 * d1;
    __syncthreads();
    for (int o = 128; o > 0; o >>= 1) { if (t < o) red[t] += red[t + o]; __syncthreads(); }
    __shared__ float rs_s;
    if (t == 0) rs_s = rsqrtf(red[0] * (1.f / Dsz) + 1e-5f);
    __syncthreads();
    float r = rs_s;
    const float* gg = lng + (size_t)i * Dsz;
    const float* bb = lnb + (size_t)i * Dsz;
    xn[(size_t)row * Dsz + t]       = d0 * r * gg[t]       + bb[t];
    xn[(size_t)row * Dsz + t + 256] = d1 * r * gg[t + 256] + bb[t + 256];
}

// ---------------- tiled SGEMM 128x128x8, 256 threads, 8x8 per thread ----------------
// Epilogues: 0 = GELU store, 1 = tanh store, 2 = block-output (torsion gate + fusion +
// residual accumulate into C), 3 = plain bias store (cross fusion; CONCAT A = [g_c|g_b])
#define GEPI_GELU  0
#define GEPI_TANH  1
#define GEPI_BLOCK 2
#define GEPI_BIAS  3

template <int EPI, bool CONCAT>
__global__ void __launch_bounds__(256, 2) gemm_kernel(
    const float* __restrict__ A, const float* __restrict__ A2,
    const float* __restrict__ Bw, const float* __restrict__ bias,
    float* __restrict__ C, int M, int N, int K,
    const float* __restrict__ gate, const float* __restrict__ torsion,
    const float* __restrict__ meanOther,
    const int* __restrict__ top, int jsel)
{
    int ii = 0;
    if (top) ii = top[jsel];
    const float* Bp  = Bw  + (size_t)ii * K * N;
    const float* bia = bias + (size_t)ii * N;
    const float* gat = gate ? gate + (size_t)ii * N : nullptr;

    __shared__ float As[8][128];
    __shared__ float Bs[8][128];
    int tid = threadIdx.x;
    int bm = blockIdx.y * 128;
    int bn = blockIdx.x * 128;
    int arow = tid >> 1, acol = (tid & 1) * 4;   // A tile loader
    int brow = tid >> 5, bcol = (tid & 31) * 4;  // B tile loader
    int tx = tid & 15, ty = tid >> 4;

    float acc[8][8];
#pragma unroll
    for (int i = 0; i < 8; i++)
#pragma unroll
        for (int j = 0; j < 8; j++) acc[i][j] = 0.f;

    for (int k0 = 0; k0 < K; k0 += 8) {
        float4 av;
        if (CONCAT) {
            int kk = k0 + acol;  // logical K = 1024, split at 512 between A and A2
            if (kk < 512) av = *(const float4*)(A  + (size_t)(bm + arow) * 512 + kk);
            else          av = *(const float4*)(A2 + (size_t)(bm + arow) * 512 + (kk - 512));
        } else {
            av = *(const float4*)(A + (size_t)(bm + arow) * K + k0 + acol);
        }
        As[acol + 0][arow] = av.x;
        As[acol + 1][arow] = av.y;
        As[acol + 2][arow] = av.z;
        As[acol + 3][arow] = av.w;
        *(float4*)&Bs[brow][bcol] = *(const float4*)(Bp + (size_t)(k0 + brow) * N + bn + bcol);
        __syncthreads();
#pragma unroll
        for (int k = 0; k < 8; k++) {
            float ra[8], rb[8];
#pragma unroll
            for (int i = 0; i < 8; i++) ra[i] = As[k][ty * 8 + i];
#pragma unroll
            for (int j = 0; j < 8; j++) rb[j] = Bs[k][tx * 8 + j];
#pragma unroll
            for (int i = 0; i < 8; i++)
#pragma unroll
                for (int j = 0; j < 8; j++)
                    acc[i][j] = fmaf(ra[i], rb[j], acc[i][j]);
        }
        __syncthreads();
    }

#pragma unroll
    for (int i = 0; i < 8; i++) {
        int r = bm + ty * 8 + i;
#pragma unroll
        for (int j = 0; j < 8; j++) {
            int cdx = bn + tx * 8 + j;
            float v = acc[i][j] + bia[cdx];
            size_t off = (size_t)r * N + cdx;
            if (EPI == GEPI_GELU) {
                C[off] = v * 0.5f * (1.0f + erff(v * 0.7071067811865475f));
            } else if (EPI == GEPI_TANH) {
                C[off] = tanhf(v);
            } else if (EPI == GEPI_BIAS) {
                C[off] = v;
            } else { // GEPI_BLOCK: torsion gate + cross-pathway fusion + residual
                float tg  = 1.f / (1.f + expf(-gat[cdx]));
                float sig = meanOther[(size_t)(r >> 9) * Dsz + cdx] * 0.3f; // batch = row/512
                float h   = v * (1.f + tg * torsion[cdx]) + sig * tg;
                C[off] += 0.5f * h;
            }
        }
    }
}

// ---------------- host orchestration ----------------
extern "C" void kernel_launch(void* const* d_in, const int* in_sizes, int n_in,
                              void* d_out, int out_size) {
    const float* in_c   = (const float*)d_in[0];
    const float* in_b   = (const float*)d_in[1];
    const float* tors   = (const float*)d_in[2];
    const float* wsel_c = (const float*)d_in[3];
    const float* bsel_c = (const float*)d_in[4];
    const float* wsel_b = (const float*)d_in[5];
    const float* bsel_b = (const float*)d_in[6];
    const float* clng   = (const float*)d_in[7];
    const float* clnb   = (const float*)d_in[8];
    const float* cw1    = (const float*)d_in[9];
    const float* cb1    = (const float*)d_in[10];
    const float* cw2    = (const float*)d_in[11];
    const float* cb2    = (const float*)d_in[12];
    const float* cg     = (const float*)d_in[13];
    const float* blng   = (const float*)d_in[14];
    const float* blnb   = (const float*)d_in[15];
    const float* bw1    = (const float*)d_in[16];
    const float* bb1    = (const float*)d_in[17];
    const float* bw2    = (const float*)d_in[18];
    const float* bb2    = (const float*)d_in[19];
    const float* bg     = (const float*)d_in[20];
    const float* wcr    = (const float*)d_in[21];
    const float* bcr    = (const float*)d_in[22];
    float* out = (float*)d_out;

    float *pc, *pb, *pxn, *ph1, *pmc, *pmb;
    int *ptc, *ptb;
    cudaGetSymbolAddress((void**)&pc,  g_c);
    cudaGetSymbolAddress((void**)&pb,  g_b);
    cudaGetSymbolAddress((void**)&pxn, g_xn);
    cudaGetSymbolAddress((void**)&ph1, g_h1);
    cudaGetSymbolAddress((void**)&pmc, g_mean_c);
    cudaGetSymbolAddress((void**)&pmb, g_mean_b);
    cudaGetSymbolAddress((void**)&ptc, g_top_c);
    cudaGetSymbolAddress((void**)&ptb, g_top_b);

    cudaMemcpyAsync(pc, in_c, (size_t)BSD * 4, cudaMemcpyDeviceToDevice, 0);
    cudaMemcpyAsync(pb, in_b, (size_t)BSD * 4, cudaMemcpyDeviceToDevice, 0);

    dim3 gN4(512 / 128, Msz / 128);   // N=512 GEMMs
    dim3 gN8(1024 / 128, Msz / 128);  // N=1024 GEMM

    for (int l = 0; l < LNUM; l++) {
        // layer-start means (signals + routing use pre-update states)
        colmean_kernel<<<dim3(Bsz, 2), 256>>>(pc, pmc);
        colmean_kernel<<<dim3(Bsz, 2), 256>>>(pb, pmb);
        route_kernel<<<1, 256>>>(pmc, wsel_c + (size_t)l * Dsz * NB, bsel_c + l * NB, ptc);
        route_kernel<<<1, 256>>>(pmb, wsel_b + (size_t)l * Dsz * NB, bsel_b + l * NB, ptb);

        // cortical pathway: 2 routed blocks, D->2D gelu 2D->D
        for (int j = 0; j < 2; j++) {
            ln_kernel<<<Msz, 256>>>(pc, pxn, clng + (size_t)l * NB * Dsz,
                                    clnb + (size_t)l * NB * Dsz, ptc, j);
            gemm_kernel<GEPI_GELU, false><<<gN8, 256>>>(
                pxn, nullptr, cw1 + (size_t)l * NB * Dsz * 2 * Dsz,
                cb1 + (size_t)l * NB * 2 * Dsz, ph1, Msz, 1024, 512,
                nullptr, nullptr, nullptr, ptc, j);
            gemm_kernel<GEPI_BLOCK, false><<<gN4, 256>>>(
                ph1, nullptr, cw2 + (size_t)l * NB * 2 * Dsz * Dsz,
                cb2 + (size_t)l * NB * Dsz, pc, Msz, 512, 1024,
                cg + (size_t)l * NB * Dsz, tors, pmb, ptc, j);
        }
        // brainstem pathway: 2 routed blocks, D->D tanh D->D
        for (int j = 0; j < 2; j++) {
            ln_kernel<<<Msz, 256>>>(pb, pxn, blng + (size_t)l * NB * Dsz,
                                    blnb + (size_t)l * NB * Dsz, ptb, j);
            gemm_kernel<GEPI_TANH, false><<<gN4, 256>>>(
                pxn, nullptr, bw1 + (size_t)l * NB * Dsz * Dsz,
                bb1 + (size_t)l * NB * Dsz, ph1, Msz, 512, 512,
                nullptr, nullptr, nullptr, ptb, j);
            gemm_kernel<GEPI_BLOCK, false><<<gN4, 256>>>(
                ph1, nullptr, bw2 + (size_t)l * NB * Dsz * Dsz,
                bb2 + (size_t)l * NB * Dsz, pb, Msz, 512, 512,
                bg + (size_t)l * NB * Dsz, tors, pmc, ptb, j);
        }
    }

    // fused = concat([c, b], -1) @ w_cross[3] + b_cross[3]  (only last layer matters)
    gemm_kernel<GEPI_BIAS, true><<<gN4, 256>>>(
        pc, pb, wcr + (size_t)3 * 2 * Dsz * Dsz, bcr + (size_t)3 * Dsz,
        out + 2 * (size_t)BSD, Msz, 512, 1024,
        nullptr, nullptr, nullptr, nullptr, 0);

    // outputs: [c | b | fused]
    cudaMemcpyAsync(out,        pc, (size_t)BSD * 4, cudaMemcpyDeviceToDevice, 0);
    cudaMemcpyAsync(out + BSD,  pb, (size_t)BSD * 4, cudaMemcpyDeviceToDevice, 0);
}

// round 3
// speedup vs baseline: 2.3277x; 2.3277x over previous
#include <cuda_runtime.h>
#include <math.h>
#include <stdint.h>

// Problem constants
#define LNUM 4
#define NB   8
#define Bsz  16
#define Ssz  512
#define Dsz  512
#define Msz  (Bsz * Ssz)          // 8192
#define BSD  (Bsz * Ssz * Dsz)

// ---------------- device scratch ----------------
__device__ float g_c[BSD];
__device__ float g_b[BSD];
__device__ float g_xn[BSD];                  // LN output (tf32-rounded); also concat copy of c
__device__ float g_h1[Bsz * Ssz * 2 * Dsz];  // GEMM1 output (rounded); also concat copy of b
__device__ float g_mean_c[Bsz * Dsz];
__device__ float g_mean_b[Bsz * Dsz];
__device__ int   g_top_c[2];
__device__ int   g_top_b[2];
// transposed + tf32-rounded weights, [N,K] per (layer, block)
__device__ float g_cw1T[4 * 8 * 1024 * 512];
__device__ float g_cw2T[4 * 8 * 512 * 1024];
__device__ float g_bw1T[4 * 8 * 512 * 512];
__device__ float g_bw2T[4 * 8 * 512 * 512];
__device__ float g_wcrT[512 * 1024];

// ---------------- helpers ----------------
__device__ __forceinline__ uint32_t smem_u32(const void* p) {
    uint32_t a;
    asm("{ .reg .u64 t; cvta.to.shared.u64 t, %1; cvt.u32.u64 %0, t; }" : "=r"(a) : "l"(p));
    return a;
}
__device__ __forceinline__ float rna_tf32(float x) {
    uint32_t u;
    asm("cvt.rna.tf32.f32 %0, %1;" : "=r"(u) : "f"(x));
    return __uint_as_float(u);
}
__device__ __forceinline__ void cp_async16(uint32_t saddr, const void* gaddr) {
    asm volatile("cp.async.cg.shared.global [%0], [%1], 16;" :: "r"(saddr), "l"(gaddr) : "memory");
}
__device__ __forceinline__ void cp_commit() {
    asm volatile("cp.async.commit_group;" ::: "memory");
}
template <int N>
__device__ __forceinline__ void cp_wait() {
    asm volatile("cp.async.wait_group %0;" :: "n"(N) : "memory");
}
__device__ __forceinline__ void mma_tf32(float* c, const uint32_t* a, const uint32_t* b) {
    asm volatile(
        "mma.sync.aligned.m16n8k8.row.col.f32.tf32.tf32.f32 "
        "{%0,%1,%2,%3}, {%4,%5,%6,%7}, {%8,%9}, {%0,%1,%2,%3};"
        : "+f"(c[0]), "+f"(c[1]), "+f"(c[2]), "+f"(c[3])
        : "r"(a[0]), "r"(a[1]), "r"(a[2]), "r"(a[3]), "r"(b[0]), "r"(b[1]));
}

// ---------------- small kernels ----------------
__global__ void colmean_kernel(const float* __restrict__ x, float* __restrict__ out) {
    int b = blockIdx.x;
    int d = blockIdx.y * 256 + threadIdx.x;
    const float* p = x + (size_t)b * Ssz * Dsz + d;
    float s = 0.f;
#pragma unroll 8
    for (int t = 0; t < Ssz; t++) s += p[(size_t)t * Dsz];
    out[b * Dsz + d] = s * (1.0f / Ssz);
}

__global__ void route_kernel(const float* __restrict__ mean0, const float* __restrict__ wsel,
                             const float* __restrict__ bsel, int* __restrict__ top) {
    int lane = threadIdx.x & 31, w = threadIdx.x >> 5;
    float s = 0.f;
    for (int d = lane; d < Dsz; d += 32) s += mean0[d] * wsel[d * NB + w];
#pragma unroll
    for (int o = 16; o > 0; o >>= 1) s += __shfl_down_sync(0xffffffffu, s, o);
    __shared__ float adj[NB];
    if (lane == 0) {
        float sc = 1.f / (1.f + expf(-(s + bsel[w])));
        adj[w] = sc * 0.7f + 0.15f;
    }
    __syncthreads();
    if (threadIdx.x == 0) {
        int i1 = 0; float v1 = adj[0];
        for (int n = 1; n < NB; n++) if (adj[n] > v1) { v1 = adj[n]; i1 = n; }
        int i2 = -1; float v2 = -1e30f;
        for (int n = 0; n < NB; n++) if (n != i1 && adj[n] > v2) { v2 = adj[n]; i2 = n; }
        top[0] = i1; top[1] = i2;
    }
}

// LayerNorm; output tf32-rounded (GEMM consumes it directly)
__global__ void ln_kernel(const float* __restrict__ x, float* __restrict__ xn,
                          const float* __restrict__ lng, const float* __restrict__ lnb,
                          const int* __restrict__ top, int jsel) {
    int i = top[jsel];
    int row = blockIdx.x;
    const float* xr = x + (size_t)row * Dsz;
    int t = threadIdx.x;
    float v0 = xr[t], v1 = xr[t + 256];
    __shared__ float red[256];
    red[t] = v0 + v1;
    __syncthreads();
    for (int o = 128; o > 0; o >>= 1) { if (t < o) red[t] += red[t + o]; __syncthreads(); }
    __shared__ float mu_s;
    if (t == 0) mu_s = red[0] * (1.f / Dsz);
    __syncthreads();
    float m = mu_s;
    float d0 = v0 - m, d1 = v1 - m;
    red[t] = d0 * d0 + d1 * d1;
    __syncthreads();
    for (int o = 128; o > 0; o >>= 1) { if (t < o) red[t] += red[t + o]; __syncthreads(); }
    __shared__ float rs_s;
    if (t == 0) rs_s = rsqrtf(red[0] * (1.f / Dsz) + 1e-5f);
    __syncthreads();
    float r = rs_s;
    const float* gg = lng + (size_t)i * Dsz;
    const float* bb = lnb + (size_t)i * Dsz;
    xn[(size_t)row * Dsz + t]       = rna_tf32(d0 * r * gg[t]       + bb[t]);
    xn[(size_t)row * Dsz + t + 256] = rna_tf32(d1 * r * gg[t + 256] + bb[t + 256]);
}

// W [K,N] -> WT [N,K], tf32 round-to-nearest
__global__ void transpose_rna_kernel(const float* __restrict__ W, float* __restrict__ WT,
                                     int K, int N) {
    __shared__ float tile[32][33];
    const float* Wz = W + (size_t)blockIdx.z * K * N;
    float* Tz = WT + (size_t)blockIdx.z * K * N;
    int x = blockIdx.x * 32 + threadIdx.x;
    int y0 = blockIdx.y * 32;
#pragma unroll
    for (int j = 0; j < 4; j++)
        tile[threadIdx.y + j * 8][threadIdx.x] = Wz[(size_t)(y0 + threadIdx.y + j * 8) * N + x];
    __syncthreads();
    int x2 = blockIdx.y * 32 + threadIdx.x;
    int y2 = blockIdx.x * 32;
#pragma unroll
    for (int j = 0; j < 4; j++)
        Tz[(size_t)(y2 + threadIdx.y + j * 8) * K + x2] = rna_tf32(tile[threadIdx.x][threadIdx.y + j * 8]);
}

// elementwise tf32-round copy (for concat GEMM inputs)
__global__ void rna_copy_kernel(const float* __restrict__ in, float* __restrict__ out, int n4) {
    int i = blockIdx.x * 256 + threadIdx.x;
    if (i < n4) {
        float4 v = ((const float4*)in)[i];
        v.x = rna_tf32(v.x); v.y = rna_tf32(v.y);
        v.z = rna_tf32(v.z); v.w = rna_tf32(v.w);
        ((float4*)out)[i] = v;
    }
}

// ---------------- mma.sync tf32 GEMM: 128x128 tile, BK=32, cp.async 2-stage ----------------
#define GEPI_GELU  0
#define GEPI_TANH  1
#define GEPI_BLOCK 2
#define GEPI_BIAS  3

#define KPAD 36
#define TILE_FLOATS (128 * KPAD)                 // 4608 floats = 18432 B
#define MMA_SMEM_BYTES (4 * TILE_FLOATS * 4)     // A0 B0 A1 B1 = 73728 B

template <int EPI, bool CONCAT>
__global__ void __launch_bounds__(256) mma_gemm(
    const float* __restrict__ A, const float* __restrict__ A2,
    const float* __restrict__ BT, const float* __restrict__ bias,
    float* __restrict__ C, int M, int N, int K,
    const float* __restrict__ gate, const float* __restrict__ torsion,
    const float* __restrict__ meanOther,
    const int* __restrict__ top, int jsel)
{
    extern __shared__ float smf[];
    float* sA[2] = { smf,                   smf + 2 * TILE_FLOATS };
    float* sB[2] = { smf + TILE_FLOATS,     smf + 3 * TILE_FLOATS };

    int tid = threadIdx.x;
    int wid = tid >> 5, lane = tid & 31;
    int g = lane >> 2, t = lane & 3;
    int wm = wid & 3, wn = wid >> 2;            // 4x2 warp grid; warp tile 32(m) x 64(n)
    int bm = blockIdx.y * 128;
    int bn = blockIdx.x * 128;

    int ii = 0;
    if (top) ii = top[jsel];
    const float* Bp  = BT   + (size_t)ii * K * N + (size_t)bn * K;  // [N,K] rows
    const float* bia = bias + (size_t)ii * N;

    // cp.async loader: 4 chunks of 16B per thread per tile
    int lrow = tid >> 1;                    // 0..127 (2 chunks per row pair)... use idx math
    (void)lrow;
    uint32_t sbase = smem_u32(smf);

    auto load_tile = [&](int c) {
        int p = c & 1;
        int k0 = c << 5;
        uint32_t sAa = sbase + (uint32_t)((p ? 2 : 0) * TILE_FLOATS) * 4;
        uint32_t sBa = sbase + (uint32_t)((p ? 3 : 1) * TILE_FLOATS) * 4;
#pragma unroll
        for (int i = 0; i < 4; i++) {
            int idx = i * 256 + tid;          // 0..1023
            int row = idx >> 3;               // 0..127
            int kc  = (idx & 7) * 4;          // 0,4,...,28
            const float* gsrc;
            if (CONCAT) {
                int kk = k0 + kc;
                gsrc = (kk < 512) ? (A + (size_t)(bm + row) * 512 + kk)
                                  : (A2 + (size_t)(bm + row) * 512 + (kk - 512));
            } else {
                gsrc = A + (size_t)(bm + row) * K + k0 + kc;
            }
            cp_async16(sAa + (uint32_t)(row * KPAD + kc) * 4, gsrc);
            cp_async16(sBa + (uint32_t)(row * KPAD + kc) * 4, Bp + (size_t)row * K + k0 + kc);
        }
        cp_commit();
    };

    float acc[2][8][4];
#pragma unroll
    for (int a = 0; a < 2; a++)
#pragma unroll
        for (int b = 0; b < 8; b++)
#pragma unroll
            for (int q = 0; q < 4; q++) acc[a][b][q] = 0.f;

    const int nk = K >> 5;
    load_tile(0);

    for (int c = 0; c < nk; c++) {
        if (c + 1 < nk) { load_tile(c + 1); cp_wait<1>(); }
        else            { cp_wait<0>(); }
        __syncthreads();

        const float* cA = sA[c & 1];
        const float* cB = sB[c & 1];
#pragma unroll
        for (int s = 0; s < 4; s++) {
            uint32_t af[2][4], bf[8][2];
#pragma unroll
            for (int mt = 0; mt < 2; mt++) {
                int mb = wm * 32 + mt * 16;
                const float* pa = cA + (mb + g) * KPAD + s * 8 + t;
                af[mt][0] = __float_as_uint(pa[0]);
                af[mt][1] = __float_as_uint(pa[8 * KPAD]);
                af[mt][2] = __float_as_uint(pa[4]);
                af[mt][3] = __float_as_uint(pa[8 * KPAD + 4]);
            }
#pragma unroll
            for (int nt = 0; nt < 8; nt++) {
                int nb = wn * 64 + nt * 8;
                const float* pb = cB + (nb + g) * KPAD + s * 8 + t;
                bf[nt][0] = __float_as_uint(pb[0]);
                bf[nt][1] = __float_as_uint(pb[4]);
            }
#pragma unroll
            for (int mt = 0; mt < 2; mt++)
#pragma unroll
                for (int nt = 0; nt < 8; nt++)
                    mma_tf32(acc[mt][nt], af[mt], bf[nt]);
        }
        __syncthreads();
    }

    // ---------------- epilogue ----------------
#pragma unroll
    for (int mt = 0; mt < 2; mt++) {
        int m0 = bm + wm * 32 + mt * 16 + g;
#pragma unroll
        for (int half = 0; half < 2; half++) {
            int m = m0 + half * 8;
            int batch = m >> 9;
#pragma unroll
            for (int nt = 0; nt < 8; nt++) {
                int n = bn + wn * 64 + nt * 8 + t * 2;
                float v0 = acc[mt][nt][half * 2 + 0] + bia[n];
                float v1 = acc[mt][nt][half * 2 + 1] + bia[n + 1];
                float2 o;
                if (EPI == GEPI_GELU) {
                    o.x = rna_tf32(v0 * 0.5f * (1.0f + erff(v0 * 0.7071067811865475f)));
                    o.y = rna_tf32(v1 * 0.5f * (1.0f + erff(v1 * 0.7071067811865475f)));
                } else if (EPI == GEPI_TANH) {
                    o.x = rna_tf32(tanhf(v0));
                    o.y = rna_tf32(tanhf(v1));
                } else if (EPI == GEPI_BIAS) {
                    o.x = v0; o.y = v1;
                } else {
                    const float* gp = gate + (size_t)ii * N;
                    float tg0 = 1.f / (1.f + expf(-gp[n]));
                    float tg1 = 1.f / (1.f + expf(-gp[n + 1]));
                    float s0 = meanOther[(size_t)batch * Dsz + n] * 0.3f;
                    float s1 = meanOther[(size_t)batch * Dsz + n + 1] * 0.3f;
                    float h0 = v0 * (1.f + tg0 * torsion[n])     + s0 * tg0;
                    float h1 = v1 * (1.f + tg1 * torsion[n + 1]) + s1 * tg1;
                    float2 old = *(const float2*)(C + (size_t)m * N + n);
                    o.x = old.x + 0.5f * h0;
                    o.y = old.y + 0.5f * h1;
                }
                *(float2*)(C + (size_t)m * N + n) = o;
            }
        }
    }
}

// ---------------- host orchestration ----------------
extern "C" void kernel_launch(void* const* d_in, const int* in_sizes, int n_in,
                              void* d_out, int out_size) {
    const float* in_c   = (const float*)d_in[0];
    const float* in_b   = (const float*)d_in[1];
    const float* tors   = (const float*)d_in[2];
    const float* wsel_c = (const float*)d_in[3];
    const float* bsel_c = (const float*)d_in[4];
    const float* wsel_b = (const float*)d_in[5];
    const float* bsel_b = (const float*)d_in[6];
    const float* clng   = (const float*)d_in[7];
    const float* clnb   = (const float*)d_in[8];
    const float* cw1    = (const float*)d_in[9];
    const float* cb1    = (const float*)d_in[10];
    const float* cw2    = (const float*)d_in[11];
    const float* cb2    = (const float*)d_in[12];
    const float* cg     = (const float*)d_in[13];
    const float* blng   = (const float*)d_in[14];
    const float* blnb   = (const float*)d_in[15];
    const float* bw1    = (const float*)d_in[16];
    const float* bb1    = (const float*)d_in[17];
    const float* bw2    = (const float*)d_in[18];
    const float* bb2    = (const float*)d_in[19];
    const float* bg     = (const float*)d_in[20];
    const float* wcr    = (const float*)d_in[21];
    const float* bcr    = (const float*)d_in[22];
    float* out = (float*)d_out;

    float *pc, *pb, *pxn, *ph1, *pmc, *pmb;
    float *pcw1T, *pcw2T, *pbw1T, *pbw2T, *pwcrT;
    int *ptc, *ptb;
    cudaGetSymbolAddress((void**)&pc,  g_c);
    cudaGetSymbolAddress((void**)&pb,  g_b);
    cudaGetSymbolAddress((void**)&pxn, g_xn);
    cudaGetSymbolAddress((void**)&ph1, g_h1);
    cudaGetSymbolAddress((void**)&pmc, g_mean_c);
    cudaGetSymbolAddress((void**)&pmb, g_mean_b);
    cudaGetSymbolAddress((void**)&ptc, g_top_c);
    cudaGetSymbolAddress((void**)&ptb, g_top_b);
    cudaGetSymbolAddress((void**)&pcw1T, g_cw1T);
    cudaGetSymbolAddress((void**)&pcw2T, g_cw2T);
    cudaGetSymbolAddress((void**)&pbw1T, g_bw1T);
    cudaGetSymbolAddress((void**)&pbw2T, g_bw2T);
    cudaGetSymbolAddress((void**)&pwcrT, g_wcrT);

    cudaFuncSetAttribute(mma_gemm<GEPI_GELU,  false>, cudaFuncAttributeMaxDynamicSharedMemorySize, MMA_SMEM_BYTES);
    cudaFuncSetAttribute(mma_gemm<GEPI_TANH,  false>, cudaFuncAttributeMaxDynamicSharedMemorySize, MMA_SMEM_BYTES);
    cudaFuncSetAttribute(mma_gemm<GEPI_BLOCK, false>, cudaFuncAttributeMaxDynamicSharedMemorySize, MMA_SMEM_BYTES);
    cudaFuncSetAttribute(mma_gemm<GEPI_BIAS,  true >, cudaFuncAttributeMaxDynamicSharedMemorySize, MMA_SMEM_BYTES);

    cudaMemcpyAsync(pc, in_c, (size_t)BSD * 4, cudaMemcpyDeviceToDevice, 0);
    cudaMemcpyAsync(pb, in_b, (size_t)BSD * 4, cudaMemcpyDeviceToDevice, 0);

    dim3 tb(32, 8);
    transpose_rna_kernel<<<dim3(32, 16, 32), tb>>>(cw1, pcw1T, 512, 1024);
    transpose_rna_kernel<<<dim3(16, 32, 32), tb>>>(cw2, pcw2T, 1024, 512);
    transpose_rna_kernel<<<dim3(16, 16, 32), tb>>>(bw1, pbw1T, 512, 512);
    transpose_rna_kernel<<<dim3(16, 16, 32), tb>>>(bw2, pbw2T, 512, 512);
    transpose_rna_kernel<<<dim3(16, 32, 1),  tb>>>(wcr + (size_t)3 * 1024 * 512, pwcrT, 1024, 512);

    dim3 gN4(4, Msz / 128);
    dim3 gN8(8, Msz / 128);

    for (int l = 0; l < LNUM; l++) {
        colmean_kernel<<<dim3(Bsz, 2), 256>>>(pc, pmc);
        colmean_kernel<<<dim3(Bsz, 2), 256>>>(pb, pmb);
        route_kernel<<<1, 256>>>(pmc, wsel_c + (size_t)l * Dsz * NB, bsel_c + l * NB, ptc);
        route_kernel<<<1, 256>>>(pmb, wsel_b + (size_t)l * Dsz * NB, bsel_b + l * NB, ptb);

        for (int j = 0; j < 2; j++) {
            ln_kernel<<<Msz, 256>>>(pc, pxn, clng + (size_t)l * NB * Dsz,
                                    clnb + (size_t)l * NB * Dsz, ptc, j);
            mma_gemm<GEPI_GELU, false><<<gN8, 256, MMA_SMEM_BYTES>>>(
                pxn, nullptr, pcw1T + (size_t)l * NB * 1024 * 512,
                cb1 + (size_t)l * NB * 1024, ph1, Msz, 1024, 512,
                nullptr, nullptr, nullptr, ptc, j);
            mma_gemm<GEPI_BLOCK, false><<<gN4, 256, MMA_SMEM_BYTES>>>(
                ph1, nullptr, pcw2T + (size_t)l * NB * 512 * 1024,
                cb2 + (size_t)l * NB * 512, pc, Msz, 512, 1024,
                cg + (size_t)l * NB * Dsz, tors, pmb, ptc, j);
        }
        for (int j = 0; j < 2; j++) {
            ln_kernel<<<Msz, 256>>>(pb, pxn, blng + (size_t)l * NB * Dsz,
                                    blnb + (size_t)l * NB * Dsz, ptb, j);
            mma_gemm<GEPI_TANH, false><<<gN4, 256, MMA_SMEM_BYTES>>>(
                pxn, nullptr, pbw1T + (size_t)l * NB * 512 * 512,
                bb1 + (size_t)l * NB * 512, ph1, Msz, 512, 512,
                nullptr, nullptr, nullptr, ptb, j);
            mma_gemm<GEPI_BLOCK, false><<<gN4, 256, MMA_SMEM_BYTES>>>(
                ph1, nullptr, pbw2T + (size_t)l * NB * 512 * 512,
                bb2 + (size_t)l * NB * 512, pb, Msz, 512, 512,
                bg + (size_t)l * NB * Dsz, tors, pmc, ptb, j);
        }
    }

    // concat GEMM: pre-round states into scratch, then fused = [c|b] @ wcrT + bcr
    rna_copy_kernel<<<(BSD / 4 + 255) / 256, 256>>>(pc, pxn, BSD / 4);
    rna_copy_kernel<<<(BSD / 4 + 255) / 256, 256>>>(pb, ph1, BSD / 4);
    mma_gemm<GEPI_BIAS, true><<<gN4, 256, MMA_SMEM_BYTES>>>(
        pxn, ph1, pwcrT, bcr + (size_t)3 * Dsz,
        out + 2 * (size_t)BSD, Msz, 512, 1024,
        nullptr, nullptr, nullptr, nullptr, 0);

    cudaMemcpyAsync(out,       pc, (size_t)BSD * 4, cudaMemcpyDeviceToDevice, 0);
    cudaMemcpyAsync(out + BSD, pb, (size_t)BSD * 4, cudaMemcpyDeviceToDevice, 0);
}

// round 4
// speedup vs baseline: 3.9319x; 1.6892x over previous
#include <cuda_runtime.h>
#include <cuda_fp16.h>
#include <math.h>
#include <stdint.h>

// Problem constants
#define LNUM 4
#define NB   8
#define Bsz  16
#define Ssz  512
#define Dsz  512
#define Msz  (Bsz * Ssz)          // 8192
#define BSD  (Bsz * Ssz * Dsz)

// ---------------- device scratch ----------------
__device__ float  g_c[BSD];
__device__ float  g_b[BSD];
__device__ __half g_xnh[BSD];                   // LN out (half); concat copy of c
__device__ __half g_h1h[Bsz * Ssz * 2 * Dsz];   // GEMM1 out (half); concat copy of b
__device__ float  g_mean_c[Bsz * Dsz];
__device__ float  g_mean_b[Bsz * Dsz];
__device__ int    g_top_c[2];
__device__ int    g_top_b[2];
// transposed half weights [N,K] per (layer, block); only routed slots filled
__device__ __half g_cw1T[4 * 8 * 1024 * 512];
__device__ __half g_cw2T[4 * 8 * 512 * 1024];
__device__ __half g_bw1T[4 * 8 * 512 * 512];
__device__ __half g_bw2T[4 * 8 * 512 * 512];
__device__ __half g_wcrT[512 * 1024];

// ---------------- helpers ----------------
__device__ __forceinline__ uint32_t smem_u32(const void* p) {
    uint32_t a;
    asm("{ .reg .u64 t; cvta.to.shared.u64 t, %1; cvt.u32.u64 %0, t; }" : "=r"(a) : "l"(p));
    return a;
}
__device__ __forceinline__ void cp_async16(uint32_t saddr, const void* gaddr) {
    asm volatile("cp.async.cg.shared.global [%0], [%1], 16;" :: "r"(saddr), "l"(gaddr) : "memory");
}
__device__ __forceinline__ void cp_commit() {
    asm volatile("cp.async.commit_group;" ::: "memory");
}
template <int N>
__device__ __forceinline__ void cp_wait() {
    asm volatile("cp.async.wait_group %0;" :: "n"(N) : "memory");
}
__device__ __forceinline__ void mma_f16(float* c, const uint32_t* a, const uint32_t* b) {
    asm volatile(
        "mma.sync.aligned.m16n8k16.row.col.f32.f16.f16.f32 "
        "{%0,%1,%2,%3}, {%4,%5,%6,%7}, {%8,%9}, {%0,%1,%2,%3};"
        : "+f"(c[0]), "+f"(c[1]), "+f"(c[2]), "+f"(c[3])
        : "r"(a[0]), "r"(a[1]), "r"(a[2]), "r"(a[3]), "r"(b[0]), "r"(b[1]));
}
__device__ __forceinline__ float warp_sum(float v) {
#pragma unroll
    for (int o = 16; o > 0; o >>= 1) v += __shfl_xor_sync(0xffffffffu, v, o);
    return v;
}

// ---------------- small kernels ----------------
__global__ void colmean_kernel(const float* __restrict__ x, float* __restrict__ out) {
    int b = blockIdx.x;
    int d = blockIdx.y * 256 + threadIdx.x;
    const float* p = x + (size_t)b * Ssz * Dsz + d;
    float s = 0.f;
#pragma unroll 8
    for (int t = 0; t < Ssz; t++) s += p[(size_t)t * Dsz];
    out[b * Dsz + d] = s * (1.0f / Ssz);
}

__global__ void route_kernel(const float* __restrict__ mean0, const float* __restrict__ wsel,
                             const float* __restrict__ bsel, int* __restrict__ top) {
    int lane = threadIdx.x & 31, w = threadIdx.x >> 5;
    float s = 0.f;
    for (int d = lane; d < Dsz; d += 32) s += mean0[d] * wsel[d * NB + w];
#pragma unroll
    for (int o = 16; o > 0; o >>= 1) s += __shfl_down_sync(0xffffffffu, s, o);
    __shared__ float adj[NB];
    if (lane == 0) {
        float sc = 1.f / (1.f + expf(-(s + bsel[w])));
        adj[w] = sc * 0.7f + 0.15f;
    }
    __syncthreads();
    if (threadIdx.x == 0) {
        int i1 = 0; float v1 = adj[0];
        for (int n = 1; n < NB; n++) if (adj[n] > v1) { v1 = adj[n]; i1 = n; }
        int i2 = -1; float v2 = -1e30f;
        for (int n = 0; n < NB; n++) if (n != i1 && adj[n] > v2) { v2 = adj[n]; i2 = n; }
        top[0] = i1; top[1] = i2;
    }
}

// warp-per-row LayerNorm, writes half
__global__ void ln_kernel(const float* __restrict__ x, __half* __restrict__ xn,
                          const float* __restrict__ lng, const float* __restrict__ lnb,
                          const int* __restrict__ top, int jsel) {
    int i = top[jsel];
    int row = blockIdx.x * 8 + (threadIdx.x >> 5);
    int lane = threadIdx.x & 31;
    const float4* xr = (const float4*)(x + (size_t)row * Dsz);
    float4 v[4];
    float s = 0.f;
#pragma unroll
    for (int q = 0; q < 4; q++) {
        v[q] = xr[lane + q * 32];
        s += v[q].x + v[q].y + v[q].z + v[q].w;
    }
    float mu = warp_sum(s) * (1.f / Dsz);
    float ss = 0.f;
#pragma unroll
    for (int q = 0; q < 4; q++) {
        float a = v[q].x - mu, b = v[q].y - mu, c = v[q].z - mu, d = v[q].w - mu;
        ss += a * a + b * b + c * c + d * d;
    }
    float r = rsqrtf(warp_sum(ss) * (1.f / Dsz) + 1e-5f);
    const float4* gg = (const float4*)(lng + (size_t)i * Dsz);
    const float4* bb = (const float4*)(lnb + (size_t)i * Dsz);
#pragma unroll
    for (int q = 0; q < 4; q++) {
        int c4 = lane + q * 32;
        float4 g = gg[c4], be = bb[c4];
        float o0 = (v[q].x - mu) * r * g.x + be.x;
        float o1 = (v[q].y - mu) * r * g.y + be.y;
        float o2 = (v[q].z - mu) * r * g.z + be.z;
        float o3 = (v[q].w - mu) * r * g.w + be.w;
        __half2 h0 = __floats2half2_rn(o0, o1);
        __half2 h1 = __floats2half2_rn(o2, o3);
        uint2 pk = make_uint2(*(uint32_t*)&h0, *(uint32_t*)&h1);
        *(uint2*)(xn + (size_t)row * Dsz + c4 * 4) = pk;
    }
}

// W [K,N] fp32 (block selected via top[z] or z) -> WT [N,K] half
__global__ void transpose_h_kernel(const float* __restrict__ W, __half* __restrict__ WT,
                                   int K, int N, const int* __restrict__ top) {
    __shared__ float tile[32][33];
    int ii = top ? top[blockIdx.z] : (int)blockIdx.z;
    const float* Wz = W + (size_t)ii * K * N;
    __half* Tz = WT + (size_t)ii * K * N;
    int x = blockIdx.x * 32 + threadIdx.x;
    int y0 = blockIdx.y * 32;
#pragma unroll
    for (int j = 0; j < 4; j++)
        tile[threadIdx.y + j * 8][threadIdx.x] = Wz[(size_t)(y0 + threadIdx.y + j * 8) * N + x];
    __syncthreads();
    int x2 = blockIdx.y * 32 + threadIdx.x;
    int y2 = blockIdx.x * 32;
#pragma unroll
    for (int j = 0; j < 4; j++)
        Tz[(size_t)(y2 + threadIdx.y + j * 8) * K + x2] = __float2half_rn(tile[threadIdx.x][threadIdx.y + j * 8]);
}

// fp32 -> half copy (for concat GEMM inputs)
__global__ void f2h_kernel(const float* __restrict__ in, __half* __restrict__ out, int n4) {
    int i = blockIdx.x * 256 + threadIdx.x;
    if (i < n4) {
        float4 v = ((const float4*)in)[i];
        __half2 h0 = __floats2half2_rn(v.x, v.y);
        __half2 h1 = __floats2half2_rn(v.z, v.w);
        *(uint2*)(out + (size_t)i * 4) = make_uint2(*(uint32_t*)&h0, *(uint32_t*)&h1);
    }
}

// ---------------- fp16 mma.sync GEMM: 128x128 tile, BK=32, 2-stage cp.async ----------------
#define GEPI_GELU  0
#define GEPI_TANH  1
#define GEPI_BLOCK 2
#define GEPI_BIAS  3

#define KPADH 40
#define TILEH (128 * KPADH)                     // halves per tile buffer
#define MMA_SMEM_BYTES (4 * TILEH * 2)          // A0 B0 A1 B1 = 40960 B

template <int EPI, bool CONCAT>
__global__ void __launch_bounds__(256, 2) mma_gemm(
    const __half* __restrict__ A, const __half* __restrict__ A2,
    const __half* __restrict__ BT, const float* __restrict__ bias,
    void* __restrict__ Cv, int M, int N, int K,
    const float* __restrict__ gate, const float* __restrict__ torsion,
    const float* __restrict__ meanOther,
    const int* __restrict__ top, int jsel)
{
    extern __shared__ __half smh[];
    __half* sA[2] = { smh,             smh + 2 * TILEH };
    __half* sB[2] = { smh + TILEH,     smh + 3 * TILEH };

    int tid = threadIdx.x;
    int wid = tid >> 5, lane = tid & 31;
    int g = lane >> 2, t = lane & 3;
    int wm = wid & 3, wn = wid >> 2;            // 4x2 warps; warp tile 32(m) x 64(n)
    int bm = blockIdx.y * 128;
    int bn = blockIdx.x * 128;

    int ii = 0;
    if (top) ii = top[jsel];
    const __half* Bp  = BT + (size_t)ii * K * N + (size_t)bn * K;
    const float*  bia = bias + (size_t)ii * N;

    uint32_t sbase = smem_u32(smh);

    auto load_tile = [&](int c) {
        int p = c & 1;
        int k0 = c << 5;
        uint32_t sAa = sbase + (uint32_t)((p ? 2 : 0) * TILEH) * 2;
        uint32_t sBa = sbase + (uint32_t)((p ? 3 : 1) * TILEH) * 2;
#pragma unroll
        for (int i = 0; i < 2; i++) {
            int idx = i * 256 + tid;          // 0..511
            int row = idx >> 2;               // 0..127
            int ch  = (idx & 3) * 8;          // half offset 0,8,16,24
            const __half* gsrc;
            if (CONCAT) {
                int kk = k0 + ch;
                gsrc = (kk < 512) ? (A + (size_t)(bm + row) * 512 + kk)
                                  : (A2 + (size_t)(bm + row) * 512 + (kk - 512));
            } else {
                gsrc = A + (size_t)(bm + row) * K + k0 + ch;
            }
            cp_async16(sAa + (uint32_t)(row * KPADH + ch) * 2, gsrc);
            cp_async16(sBa + (uint32_t)(row * KPADH + ch) * 2, Bp + (size_t)row * K + k0 + ch);
        }
        cp_commit();
    };

    float acc[2][8][4];
#pragma unroll
    for (int a = 0; a < 2; a++)
#pragma unroll
        for (int b = 0; b < 8; b++)
#pragma unroll
            for (int q = 0; q < 4; q++) acc[a][b][q] = 0.f;

    const int nk = K >> 5;
    load_tile(0);

    for (int c = 0; c < nk; c++) {
        if (c + 1 < nk) { load_tile(c + 1); cp_wait<1>(); }
        else            { cp_wait<0>(); }
        __syncthreads();

        const __half* cA = sA[c & 1];
        const __half* cB = sB[c & 1];
#pragma unroll
        for (int s = 0; s < 2; s++) {
            uint32_t af[2][4], bf[8][2];
#pragma unroll
            for (int mt = 0; mt < 2; mt++) {
                const __half* pa = cA + (wm * 32 + mt * 16 + g) * KPADH + s * 16 + t * 2;
                af[mt][0] = *(const uint32_t*)(pa);
                af[mt][1] = *(const uint32_t*)(pa + 8 * KPADH);
                af[mt][2] = *(const uint32_t*)(pa + 8);
                af[mt][3] = *(const uint32_t*)(pa + 8 * KPADH + 8);
            }
#pragma unroll
            for (int nt = 0; nt < 8; nt++) {
                const __half* pb = cB + (wn * 64 + nt * 8 + g) * KPADH + s * 16 + t * 2;
                bf[nt][0] = *(const uint32_t*)(pb);
                bf[nt][1] = *(const uint32_t*)(pb + 8);
            }
#pragma unroll
            for (int mt = 0; mt < 2; mt++)
#pragma unroll
                for (int nt = 0; nt < 8; nt++)
                    mma_f16(acc[mt][nt], af[mt], bf[nt]);
        }
        __syncthreads();
    }

    // ---------------- epilogue ----------------
#pragma unroll
    for (int mt = 0; mt < 2; mt++) {
        int m0 = bm + wm * 32 + mt * 16 + g;
#pragma unroll
        for (int half = 0; half < 2; half++) {
            int m = m0 + half * 8;
            int batch = m >> 9;
#pragma unroll
            for (int nt = 0; nt < 8; nt++) {
                int n = bn + wn * 64 + nt * 8 + t * 2;
                float v0 = acc[mt][nt][half * 2 + 0] + bia[n];
                float v1 = acc[mt][nt][half * 2 + 1] + bia[n + 1];
                if (EPI == GEPI_GELU) {
                    float o0 = v0 * 0.5f * (1.0f + erff(v0 * 0.7071067811865475f));
                    float o1 = v1 * 0.5f * (1.0f + erff(v1 * 0.7071067811865475f));
                    __half2 h = __floats2half2_rn(o0, o1);
                    *(__half2*)((__half*)Cv + (size_t)m * N + n) = h;
                } else if (EPI == GEPI_TANH) {
                    __half2 h = __floats2half2_rn(tanhf(v0), tanhf(v1));
                    *(__half2*)((__half*)Cv + (size_t)m * N + n) = h;
                } else if (EPI == GEPI_BIAS) {
                    *(float2*)((float*)Cv + (size_t)m * N + n) = make_float2(v0, v1);
                } else {
                    float* C = (float*)Cv;
                    const float* gp = gate + (size_t)ii * N;
                    float tg0 = 1.f / (1.f + expf(-gp[n]));
                    float tg1 = 1.f / (1.f + expf(-gp[n + 1]));
                    float s0 = meanOther[(size_t)batch * Dsz + n] * 0.3f;
                    float s1 = meanOther[(size_t)batch * Dsz + n + 1] * 0.3f;
                    float h0 = v0 * (1.f + tg0 * torsion[n])     + s0 * tg0;
                    float h1 = v1 * (1.f + tg1 * torsion[n + 1]) + s1 * tg1;
                    float2 old = *(const float2*)(C + (size_t)m * N + n);
                    *(float2*)(C + (size_t)m * N + n) = make_float2(old.x + 0.5f * h0, old.y + 0.5f * h1);
                }
            }
        }
    }
}

// ---------------- host orchestration ----------------
extern "C" void kernel_launch(void* const* d_in, const int* in_sizes, int n_in,
                              void* d_out, int out_size) {
    const float* in_c   = (const float*)d_in[0];
    const float* in_b   = (const float*)d_in[1];
    const float* tors   = (const float*)d_in[2];
    const float* wsel_c = (const float*)d_in[3];
    const float* bsel_c = (const float*)d_in[4];
    const float* wsel_b = (const float*)d_in[5];
    const float* bsel_b = (const float*)d_in[6];
    const float* clng   = (const float*)d_in[7];
    const float* clnb   = (const float*)d_in[8];
    const float* cw1    = (const float*)d_in[9];
    const float* cb1    = (const float*)d_in[10];
    const float* cw2    = (const float*)d_in[11];
    const float* cb2    = (const float*)d_in[12];
    const float* cg     = (const float*)d_in[13];
    const float* blng   = (const float*)d_in[14];
    const float* blnb   = (const float*)d_in[15];
    const float* bw1    = (const float*)d_in[16];
    const float* bb1    = (const float*)d_in[17];
    const float* bw2    = (const float*)d_in[18];
    const float* bb2    = (const float*)d_in[19];
    const float* bg     = (const float*)d_in[20];
    const float* wcr    = (const float*)d_in[21];
    const float* bcr    = (const float*)d_in[22];
    float* out = (float*)d_out;

    float *pc, *pb, *pmc, *pmb;
    __half *pxnh, *ph1h, *pcw1T, *pcw2T, *pbw1T, *pbw2T, *pwcrT;
    int *ptc, *ptb;
    cudaGetSymbolAddress((void**)&pc,   g_c);
    cudaGetSymbolAddress((void**)&pb,   g_b);
    cudaGetSymbolAddress((void**)&pxnh, g_xnh);
    cudaGetSymbolAddress((void**)&ph1h, g_h1h);
    cudaGetSymbolAddress((void**)&pmc,  g_mean_c);
    cudaGetSymbolAddress((void**)&pmb,  g_mean_b);
    cudaGetSymbolAddress((void**)&ptc,  g_top_c);
    cudaGetSymbolAddress((void**)&ptb,  g_top_b);
    cudaGetSymbolAddress((void**)&pcw1T, g_cw1T);
    cudaGetSymbolAddress((void**)&pcw2T, g_cw2T);
    cudaGetSymbolAddress((void**)&pbw1T, g_bw1T);
    cudaGetSymbolAddress((void**)&pbw2T, g_bw2T);
    cudaGetSymbolAddress((void**)&pwcrT, g_wcrT);

    cudaFuncSetAttribute(mma_gemm<GEPI_GELU,  false>, cudaFuncAttributeMaxDynamicSharedMemorySize, MMA_SMEM_BYTES);
    cudaFuncSetAttribute(mma_gemm<GEPI_TANH,  false>, cudaFuncAttributeMaxDynamicSharedMemorySize, MMA_SMEM_BYTES);
    cudaFuncSetAttribute(mma_gemm<GEPI_BLOCK, false>, cudaFuncAttributeMaxDynamicSharedMemorySize, MMA_SMEM_BYTES);
    cudaFuncSetAttribute(mma_gemm<GEPI_BIAS,  true >, cudaFuncAttributeMaxDynamicSharedMemorySize, MMA_SMEM_BYTES);

    cudaMemcpyAsync(pc, in_c, (size_t)BSD * 4, cudaMemcpyDeviceToDevice, 0);
    cudaMemcpyAsync(pb, in_b, (size_t)BSD * 4, cudaMemcpyDeviceToDevice, 0);

    dim3 tb(32, 8);
    // cross-fusion weights (layer 3 only, not routed)
    transpose_h_kernel<<<dim3(16, 32, 1), tb>>>(wcr + (size_t)3 * 1024 * 512, pwcrT, 1024, 512, nullptr);

    dim3 gN4(4, Msz / 128);
    dim3 gN8(8, Msz / 128);

    for (int l = 0; l < LNUM; l++) {
        colmean_kernel<<<dim3(Bsz, 2), 256>>>(pc, pmc);
        colmean_kernel<<<dim3(Bsz, 2), 256>>>(pb, pmb);
        route_kernel<<<1, 256>>>(pmc, wsel_c + (size_t)l * Dsz * NB, bsel_c + l * NB, ptc);
        route_kernel<<<1, 256>>>(pmb, wsel_b + (size_t)l * Dsz * NB, bsel_b + l * NB, ptb);

        // transpose only the two routed blocks for each pathway this layer
        transpose_h_kernel<<<dim3(32, 16, 2), tb>>>(cw1 + (size_t)l * NB * 512 * 1024,
                                                    pcw1T + (size_t)l * NB * 1024 * 512, 512, 1024, ptc);
        transpose_h_kernel<<<dim3(16, 32, 2), tb>>>(cw2 + (size_t)l * NB * 1024 * 512,
                                                    pcw2T + (size_t)l * NB * 512 * 1024, 1024, 512, ptc);
        transpose_h_kernel<<<dim3(16, 16, 2), tb>>>(bw1 + (size_t)l * NB * 512 * 512,
                                                    pbw1T + (size_t)l * NB * 512 * 512, 512, 512, ptb);
        transpose_h_kernel<<<dim3(16, 16, 2), tb>>>(bw2 + (size_t)l * NB * 512 * 512,
                                                    pbw2T + (size_t)l * NB * 512 * 512, 512, 512, ptb);

        for (int j = 0; j < 2; j++) {
            ln_kernel<<<Msz / 8, 256>>>(pc, pxnh, clng + (size_t)l * NB * Dsz,
                                        clnb + (size_t)l * NB * Dsz, ptc, j);
            mma_gemm<GEPI_GELU, false><<<gN8, 256, MMA_SMEM_BYTES>>>(
                pxnh, nullptr, pcw1T + (size_t)l * NB * 1024 * 512,
                cb1 + (size_t)l * NB * 1024, ph1h, Msz, 1024, 512,
                nullptr, nullptr, nullptr, ptc, j);
            mma_gemm<GEPI_BLOCK, false><<<gN4, 256, MMA_SMEM_BYTES>>>(
                ph1h, nullptr, pcw2T + (size_t)l * NB * 512 * 1024,
                cb2 + (size_t)l * NB * 512, pc, Msz, 512, 1024,
                cg + (size_t)l * NB * Dsz, tors, pmb, ptc, j);
        }
        for (int j = 0; j < 2; j++) {
            ln_kernel<<<Msz / 8, 256>>>(pb, pxnh, blng + (size_t)l * NB * Dsz,
                                        blnb + (size_t)l * NB * Dsz, ptb, j);
            mma_gemm<GEPI_TANH, false><<<gN4, 256, MMA_SMEM_BYTES>>>(
                pxnh, nullptr, pbw1T + (size_t)l * NB * 512 * 512,
                bb1 + (size_t)l * NB * 512, ph1h, Msz, 512, 512,
                nullptr, nullptr, nullptr, ptb, j);
            mma_gemm<GEPI_BLOCK, false><<<gN4, 256, MMA_SMEM_BYTES>>>(
                ph1h, nullptr, pbw2T + (size_t)l * NB * 512 * 512,
                bb2 + (size_t)l * NB * 512, pb, Msz, 512, 512,
                bg + (size_t)l * NB * Dsz, tors, pmc, ptb, j);
        }
    }

    // concat GEMM: half copies of the states, then fused = [c|b] @ wcrT + bcr
    f2h_kernel<<<(BSD / 4 + 255) / 256, 256>>>(pc, pxnh, BSD / 4);
    f2h_kernel<<<(BSD / 4 + 255) / 256, 256>>>(pb, ph1h, BSD / 4);
    mma_gemm<GEPI_BIAS, true><<<gN4, 256, MMA_SMEM_BYTES>>>(
        pxnh, ph1h, pwcrT, bcr + (size_t)3 * Dsz,
        out + 2 * (size_t)BSD, Msz, 512, 1024,
        nullptr, nullptr, nullptr, nullptr, 0);

    cudaMemcpyAsync(out,       pc, (size_t)BSD * 4, cudaMemcpyDeviceToDevice, 0);
    cudaMemcpyAsync(out + BSD, pb, (size_t)BSD * 4, cudaMemcpyDeviceToDevice, 0);
}

// round 5
// speedup vs baseline: 4.8169x; 1.2251x over previous
#include <cuda_runtime.h>
#include <cuda_fp16.h>
#include <math.h>
#include <stdint.h>

// Problem constants
#define LNUM 4
#define NB   8
#define Bsz  16
#define Ssz  512
#define Dsz  512
#define Msz  (Bsz * Ssz)          // 8192
#define BSD  (Bsz * Ssz * Dsz)

// ---------------- device scratch ----------------
__device__ float  g_c[BSD];
__device__ float  g_b[BSD];
__device__ __half g_xnh_c[BSD];                   // cortical LN out
__device__ __half g_xnh_b[BSD];                   // brainstem LN out
__device__ __half g_h1h_c[Bsz * Ssz * 2 * Dsz];   // cortical GEMM1 out
__device__ __half g_h1h_b[BSD];                   // brainstem GEMM1 out
__device__ __half g_cmir[BSD];                    // half mirror of final c
__device__ __half g_bmir[BSD];                    // half mirror of final b
__device__ float  g_mean_c[Bsz * Dsz];
__device__ float  g_mean_b[Bsz * Dsz];
__device__ int    g_top_c[2];
__device__ int    g_top_b[2];
// transposed half weights [N,K] per (layer, block) — ALL blocks, upfront
__device__ __half g_cw1T[4 * 8 * 1024 * 512];
__device__ __half g_cw2T[4 * 8 * 512 * 1024];
__device__ __half g_bw1T[4 * 8 * 512 * 512];
__device__ __half g_bw2T[4 * 8 * 512 * 512];
__device__ __half g_wcrT[512 * 1024];

// ---------------- helpers ----------------
__device__ __forceinline__ uint32_t smem_u32(const void* p) {
    uint32_t a;
    asm("{ .reg .u64 t; cvta.to.shared.u64 t, %1; cvt.u32.u64 %0, t; }" : "=r"(a) : "l"(p));
    return a;
}
__device__ __forceinline__ void cp_async16(uint32_t saddr, const void* gaddr) {
    asm volatile("cp.async.cg.shared.global [%0], [%1], 16;" :: "r"(saddr), "l"(gaddr) : "memory");
}
__device__ __forceinline__ void cp_commit() {
    asm volatile("cp.async.commit_group;" ::: "memory");
}
template <int N>
__device__ __forceinline__ void cp_wait() {
    asm volatile("cp.async.wait_group %0;" :: "n"(N) : "memory");
}
__device__ __forceinline__ void mma_f16(float* c, const uint32_t* a, const uint32_t* b) {
    asm volatile(
        "mma.sync.aligned.m16n8k16.row.col.f32.f16.f16.f32 "
        "{%0,%1,%2,%3}, {%4,%5,%6,%7}, {%8,%9}, {%0,%1,%2,%3};"
        : "+f"(c[0]), "+f"(c[1]), "+f"(c[2]), "+f"(c[3])
        : "r"(a[0]), "r"(a[1]), "r"(a[2]), "r"(a[3]), "r"(b[0]), "r"(b[1]));
}
__device__ __forceinline__ float warp_sum(float v) {
#pragma unroll
    for (int o = 16; o > 0; o >>= 1) v += __shfl_xor_sync(0xffffffffu, v, o);
    return v;
}

// ---------------- fused small kernels ----------------
// both-state column mean: z=0 -> c, z=1 -> b
__global__ void colmean_both_kernel(const float* __restrict__ xc, const float* __restrict__ xb,
                                    float* __restrict__ oc, float* __restrict__ ob) {
    const float* x = blockIdx.z ? xb : xc;
    float* o = blockIdx.z ? ob : oc;
    int b = blockIdx.x;
    int d = blockIdx.y * 256 + threadIdx.x;
    const float* p = x + (size_t)b * Ssz * Dsz + d;
    float s = 0.f;
#pragma unroll 8
    for (int t = 0; t < Ssz; t++) s += p[(size_t)t * Dsz];
    o[b * Dsz + d] = s * (1.0f / Ssz);
}

// both-pathway routing: block 0 -> cortical, block 1 -> brainstem
__global__ void route_both_kernel(const float* __restrict__ mc, const float* __restrict__ mb,
                                  const float* __restrict__ wc, const float* __restrict__ bc,
                                  const float* __restrict__ wb, const float* __restrict__ bbv,
                                  int* __restrict__ tc, int* __restrict__ tb) {
    const float* mean0 = blockIdx.x ? mb : mc;
    const float* wsel  = blockIdx.x ? wb : wc;
    const float* bsel  = blockIdx.x ? bbv : bc;
    int* top           = blockIdx.x ? tb : tc;
    int lane = threadIdx.x & 31, w = threadIdx.x >> 5;
    float s = 0.f;
    for (int d = lane; d < Dsz; d += 32) s += mean0[d] * wsel[d * NB + w];
#pragma unroll
    for (int o = 16; o > 0; o >>= 1) s += __shfl_down_sync(0xffffffffu, s, o);
    __shared__ float adj[NB];
    if (lane == 0) {
        float sc = 1.f / (1.f + expf(-(s + bsel[w])));
        adj[w] = sc * 0.7f + 0.15f;
    }
    __syncthreads();
    if (threadIdx.x == 0) {
        int i1 = 0; float v1 = adj[0];
        for (int n = 1; n < NB; n++) if (adj[n] > v1) { v1 = adj[n]; i1 = n; }
        int i2 = -1; float v2 = -1e30f;
        for (int n = 0; n < NB; n++) if (n != i1 && adj[n] > v2) { v2 = adj[n]; i2 = n; }
        top[0] = i1; top[1] = i2;
    }
}

// warp-per-row LayerNorm, writes half
__global__ void ln_kernel(const float* __restrict__ x, __half* __restrict__ xn,
                          const float* __restrict__ lng, const float* __restrict__ lnb,
                          const int* __restrict__ top, int jsel) {
    int i = top[jsel];
    int row = blockIdx.x * 8 + (threadIdx.x >> 5);
    int lane = threadIdx.x & 31;
    const float4* xr = (const float4*)(x + (size_t)row * Dsz);
    float4 v[4];
    float s = 0.f;
#pragma unroll
    for (int q = 0; q < 4; q++) {
        v[q] = xr[lane + q * 32];
        s += v[q].x + v[q].y + v[q].z + v[q].w;
    }
    float mu = warp_sum(s) * (1.f / Dsz);
    float ss = 0.f;
#pragma unroll
    for (int q = 0; q < 4; q++) {
        float a = v[q].x - mu, b = v[q].y - mu, c = v[q].z - mu, d = v[q].w - mu;
        ss += a * a + b * b + c * c + d * d;
    }
    float r = rsqrtf(warp_sum(ss) * (1.f / Dsz) + 1e-5f);
    const float4* gg = (const float4*)(lng + (size_t)i * Dsz);
    const float4* bb = (const float4*)(lnb + (size_t)i * Dsz);
#pragma unroll
    for (int q = 0; q < 4; q++) {
        int c4 = lane + q * 32;
        float4 g = gg[c4], be = bb[c4];
        float o0 = (v[q].x - mu) * r * g.x + be.x;
        float o1 = (v[q].y - mu) * r * g.y + be.y;
        float o2 = (v[q].z - mu) * r * g.z + be.z;
        float o3 = (v[q].w - mu) * r * g.w + be.w;
        __half2 h0 = __floats2half2_rn(o0, o1);
        __half2 h1 = __floats2half2_rn(o2, o3);
        uint2 pk = make_uint2(*(uint32_t*)&h0, *(uint32_t*)&h1);
        *(uint2*)(xn + (size_t)row * Dsz + c4 * 4) = pk;
    }
}

// W [K,N] fp32 (matrix z) -> WT [N,K] half; z covers all (layer,block) slots
__global__ void transpose_h_kernel(const float* __restrict__ W, __half* __restrict__ WT,
                                   int K, int N) {
    __shared__ float tile[32][33];
    const float* Wz = W + (size_t)blockIdx.z * K * N;
    __half* Tz = WT + (size_t)blockIdx.z * K * N;
    int x = blockIdx.x * 32 + threadIdx.x;
    int y0 = blockIdx.y * 32;
#pragma unroll
    for (int j = 0; j < 4; j++)
        tile[threadIdx.y + j * 8][threadIdx.x] = Wz[(size_t)(y0 + threadIdx.y + j * 8) * N + x];
    __syncthreads();
    int x2 = blockIdx.y * 32 + threadIdx.x;
    int y2 = blockIdx.x * 32;
#pragma unroll
    for (int j = 0; j < 4; j++)
        Tz[(size_t)(y2 + threadIdx.y + j * 8) * K + x2] = __float2half_rn(tile[threadIdx.x][threadIdx.y + j * 8]);
}

// ---------------- fp16 mma.sync GEMM: 128x128 tile, BK=32, 2-stage cp.async ----------------
#define GEPI_GELU  0
#define GEPI_TANH  1
#define GEPI_BLOCK 2
#define GEPI_BIAS  3

#define KPADH 40
#define TILEH (128 * KPADH)
#define MMA_SMEM_BYTES (4 * TILEH * 2)          // 40960 B

template <int EPI, bool CONCAT>
__global__ void __launch_bounds__(256, 2) mma_gemm(
    const __half* __restrict__ A, const __half* __restrict__ A2,
    const __half* __restrict__ BT, const float* __restrict__ bias,
    void* __restrict__ Cv, __half* __restrict__ mirror, int M, int N, int K,
    const float* __restrict__ gate, const float* __restrict__ torsion,
    const float* __restrict__ meanOther,
    const int* __restrict__ top, int jsel)
{
    extern __shared__ __half smh[];
    __half* sA[2] = { smh,             smh + 2 * TILEH };
    __half* sB[2] = { smh + TILEH,     smh + 3 * TILEH };

    int tid = threadIdx.x;
    int wid = tid >> 5, lane = tid & 31;
    int g = lane >> 2, t = lane & 3;
    int wm = wid & 3, wn = wid >> 2;
    int bm = blockIdx.y * 128;
    int bn = blockIdx.x * 128;

    int ii = 0;
    if (top) ii = top[jsel];
    const __half* Bp  = BT + (size_t)ii * K * N + (size_t)bn * K;
    const float*  bia = bias + (size_t)ii * N;

    uint32_t sbase = smem_u32(smh);

    auto load_tile = [&](int c) {
        int p = c & 1;
        int k0 = c << 5;
        uint32_t sAa = sbase + (uint32_t)((p ? 2 : 0) * TILEH) * 2;
        uint32_t sBa = sbase + (uint32_t)((p ? 3 : 1) * TILEH) * 2;
#pragma unroll
        for (int i = 0; i < 2; i++) {
            int idx = i * 256 + tid;
            int row = idx >> 2;
            int ch  = (idx & 3) * 8;
            const __half* gsrc;
            if (CONCAT) {
                int kk = k0 + ch;
                gsrc = (kk < 512) ? (A + (size_t)(bm + row) * 512 + kk)
                                  : (A2 + (size_t)(bm + row) * 512 + (kk - 512));
            } else {
                gsrc = A + (size_t)(bm + row) * K + k0 + ch;
            }
            cp_async16(sAa + (uint32_t)(row * KPADH + ch) * 2, gsrc);
            cp_async16(sBa + (uint32_t)(row * KPADH + ch) * 2, Bp + (size_t)row * K + k0 + ch);
        }
        cp_commit();
    };

    float acc[2][8][4];
#pragma unroll
    for (int a = 0; a < 2; a++)
#pragma unroll
        for (int b = 0; b < 8; b++)
#pragma unroll
            for (int q = 0; q < 4; q++) acc[a][b][q] = 0.f;

    const int nk = K >> 5;
    load_tile(0);

    for (int c = 0; c < nk; c++) {
        if (c + 1 < nk) { load_tile(c + 1); cp_wait<1>(); }
        else            { cp_wait<0>(); }
        __syncthreads();

        const __half* cA = sA[c & 1];
        const __half* cB = sB[c & 1];
#pragma unroll
        for (int s = 0; s < 2; s++) {
            uint32_t af[2][4], bf[8][2];
#pragma unroll
            for (int mt = 0; mt < 2; mt++) {
                const __half* pa = cA + (wm * 32 + mt * 16 + g) * KPADH + s * 16 + t * 2;
                af[mt][0] = *(const uint32_t*)(pa);
                af[mt][1] = *(const uint32_t*)(pa + 8 * KPADH);
                af[mt][2] = *(const uint32_t*)(pa + 8);
                af[mt][3] = *(const uint32_t*)(pa + 8 * KPADH + 8);
            }
#pragma unroll
            for (int nt = 0; nt < 8; nt++) {
                const __half* pb = cB + (wn * 64 + nt * 8 + g) * KPADH + s * 16 + t * 2;
                bf[nt][0] = *(const uint32_t*)(pb);
                bf[nt][1] = *(const uint32_t*)(pb + 8);
            }
#pragma unroll
            for (int mt = 0; mt < 2; mt++)
#pragma unroll
                for (int nt = 0; nt < 8; nt++)
                    mma_f16(acc[mt][nt], af[mt], bf[nt]);
        }
        __syncthreads();
    }

    // ---------------- epilogue ----------------
#pragma unroll
    for (int mt = 0; mt < 2; mt++) {
        int m0 = bm + wm * 32 + mt * 16 + g;
#pragma unroll
        for (int half = 0; half < 2; half++) {
            int m = m0 + half * 8;
            int batch = m >> 9;
#pragma unroll
            for (int nt = 0; nt < 8; nt++) {
                int n = bn + wn * 64 + nt * 8 + t * 2;
                float v0 = acc[mt][nt][half * 2 + 0] + bia[n];
                float v1 = acc[mt][nt][half * 2 + 1] + bia[n + 1];
                if (EPI == GEPI_GELU) {
                    float o0 = v0 * 0.5f * (1.0f + erff(v0 * 0.7071067811865475f));
                    float o1 = v1 * 0.5f * (1.0f + erff(v1 * 0.7071067811865475f));
                    *(__half2*)((__half*)Cv + (size_t)m * N + n) = __floats2half2_rn(o0, o1);
                } else if (EPI == GEPI_TANH) {
                    *(__half2*)((__half*)Cv + (size_t)m * N + n) = __floats2half2_rn(tanhf(v0), tanhf(v1));
                } else if (EPI == GEPI_BIAS) {
                    *(float2*)((float*)Cv + (size_t)m * N + n) = make_float2(v0, v1);
                } else {
                    float* C = (float*)Cv;
                    const float* gp = gate + (size_t)ii * N;
                    float tg0 = 1.f / (1.f + expf(-gp[n]));
                    float tg1 = 1.f / (1.f + expf(-gp[n + 1]));
                    float s0 = meanOther[(size_t)batch * Dsz + n] * 0.3f;
                    float s1 = meanOther[(size_t)batch * Dsz + n + 1] * 0.3f;
                    float h0 = v0 * (1.f + tg0 * torsion[n])     + s0 * tg0;
                    float h1 = v1 * (1.f + tg1 * torsion[n + 1]) + s1 * tg1;
                    float2 old = *(const float2*)(C + (size_t)m * N + n);
                    float o0 = old.x + 0.5f * h0, o1 = old.y + 0.5f * h1;
                    *(float2*)(C + (size_t)m * N + n) = make_float2(o0, o1);
                    if (mirror)
                        *(__half2*)(mirror + (size_t)m * N + n) = __floats2half2_rn(o0, o1);
                }
            }
        }
    }
}

// ---------------- host orchestration ----------------
static cudaStream_t s_sA = nullptr, s_sB = nullptr;
static cudaEvent_t  s_eF = nullptr, s_eA = nullptr, s_eB = nullptr;
static void ensure_streams() {
    if (!s_sA) {
        cudaStreamCreateWithFlags(&s_sA, cudaStreamNonBlocking);
        cudaStreamCreateWithFlags(&s_sB, cudaStreamNonBlocking);
        cudaEventCreateWithFlags(&s_eF, cudaEventDisableTiming);
        cudaEventCreateWithFlags(&s_eA, cudaEventDisableTiming);
        cudaEventCreateWithFlags(&s_eB, cudaEventDisableTiming);
    }
}

extern "C" void kernel_launch(void* const* d_in, const int* in_sizes, int n_in,
                              void* d_out, int out_size) {
    const float* in_c   = (const float*)d_in[0];
    const float* in_b   = (const float*)d_in[1];
    const float* tors   = (const float*)d_in[2];
    const float* wsel_c = (const float*)d_in[3];
    const float* bsel_c = (const float*)d_in[4];
    const float* wsel_b = (const float*)d_in[5];
    const float* bsel_b = (const float*)d_in[6];
    const float* clng   = (const float*)d_in[7];
    const float* clnb   = (const float*)d_in[8];
    const float* cw1    = (const float*)d_in[9];
    const float* cb1    = (const float*)d_in[10];
    const float* cw2    = (const float*)d_in[11];
    const float* cb2    = (const float*)d_in[12];
    const float* cg     = (const float*)d_in[13];
    const float* blng   = (const float*)d_in[14];
    const float* blnb   = (const float*)d_in[15];
    const float* bw1    = (const float*)d_in[16];
    const float* bb1    = (const float*)d_in[17];
    const float* bw2    = (const float*)d_in[18];
    const float* bb2    = (const float*)d_in[19];
    const float* bg     = (const float*)d_in[20];
    const float* wcr    = (const float*)d_in[21];
    const float* bcr    = (const float*)d_in[22];
    float* out = (float*)d_out;

    ensure_streams();

    float *pc, *pb, *pmc, *pmb;
    __half *pxnc, *pxnb, *ph1c, *ph1b, *pcm, *pbm;
    __half *pcw1T, *pcw2T, *pbw1T, *pbw2T, *pwcrT;
    int *ptc, *ptb;
    cudaGetSymbolAddress((void**)&pc,   g_c);
    cudaGetSymbolAddress((void**)&pb,   g_b);
    cudaGetSymbolAddress((void**)&pxnc, g_xnh_c);
    cudaGetSymbolAddress((void**)&pxnb, g_xnh_b);
    cudaGetSymbolAddress((void**)&ph1c, g_h1h_c);
    cudaGetSymbolAddress((void**)&ph1b, g_h1h_b);
    cudaGetSymbolAddress((void**)&pcm,  g_cmir);
    cudaGetSymbolAddress((void**)&pbm,  g_bmir);
    cudaGetSymbolAddress((void**)&pmc,  g_mean_c);
    cudaGetSymbolAddress((void**)&pmb,  g_mean_b);
    cudaGetSymbolAddress((void**)&ptc,  g_top_c);
    cudaGetSymbolAddress((void**)&ptb,  g_top_b);
    cudaGetSymbolAddress((void**)&pcw1T, g_cw1T);
    cudaGetSymbolAddress((void**)&pcw2T, g_cw2T);
    cudaGetSymbolAddress((void**)&pbw1T, g_bw1T);
    cudaGetSymbolAddress((void**)&pbw2T, g_bw2T);
    cudaGetSymbolAddress((void**)&pwcrT, g_wcrT);

    cudaFuncSetAttribute(mma_gemm<GEPI_GELU,  false>, cudaFuncAttributeMaxDynamicSharedMemorySize, MMA_SMEM_BYTES);
    cudaFuncSetAttribute(mma_gemm<GEPI_TANH,  false>, cudaFuncAttributeMaxDynamicSharedMemorySize, MMA_SMEM_BYTES);
    cudaFuncSetAttribute(mma_gemm<GEPI_BLOCK, false>, cudaFuncAttributeMaxDynamicSharedMemorySize, MMA_SMEM_BYTES);
    cudaFuncSetAttribute(mma_gemm<GEPI_BIAS,  true >, cudaFuncAttributeMaxDynamicSharedMemorySize, MMA_SMEM_BYTES);

    dim3 tb(32, 8);
    dim3 gN4(4, Msz / 128);
    dim3 gN8(8, Msz / 128);

    // ---- prologue on default stream: input copies + ALL weight transposes ----
    cudaMemcpyAsync(pc, in_c, (size_t)BSD * 4, cudaMemcpyDeviceToDevice, 0);
    cudaMemcpyAsync(pb, in_b, (size_t)BSD * 4, cudaMemcpyDeviceToDevice, 0);
    transpose_h_kernel<<<dim3(32, 16, 32), tb>>>(cw1, pcw1T, 512, 1024);
    transpose_h_kernel<<<dim3(16, 32, 32), tb>>>(cw2, pcw2T, 1024, 512);
    transpose_h_kernel<<<dim3(16, 16, 32), tb>>>(bw1, pbw1T, 512, 512);
    transpose_h_kernel<<<dim3(16, 16, 32), tb>>>(bw2, pbw2T, 512, 512);
    transpose_h_kernel<<<dim3(16, 32, 1),  tb>>>(wcr + (size_t)3 * 1024 * 512, pwcrT, 1024, 512);

    for (int l = 0; l < LNUM; l++) {
        // joined on default stream here
        colmean_both_kernel<<<dim3(Bsz, 2, 2), 256>>>(pc, pb, pmc, pmb);
        route_both_kernel<<<2, 256>>>(pmc, pmb,
                                      wsel_c + (size_t)l * Dsz * NB, bsel_c + l * NB,
                                      wsel_b + (size_t)l * Dsz * NB, bsel_b + l * NB,
                                      ptc, ptb);
        // fork
        cudaEventRecord(s_eF, 0);
        cudaStreamWaitEvent(s_sA, s_eF, 0);
        cudaStreamWaitEvent(s_sB, s_eF, 0);

        __half* cmir = (l == LNUM - 1) ? pcm : nullptr;
        __half* bmir = (l == LNUM - 1) ? pbm : nullptr;

        // stream A: cortical pathway
        for (int j = 0; j < 2; j++) {
            ln_kernel<<<Msz / 8, 256, 0, s_sA>>>(pc, pxnc, clng + (size_t)l * NB * Dsz,
                                                 clnb + (size_t)l * NB * Dsz, ptc, j);
            mma_gemm<GEPI_GELU, false><<<gN8, 256, MMA_SMEM_BYTES, s_sA>>>(
                pxnc, nullptr, pcw1T + (size_t)l * NB * 1024 * 512,
                cb1 + (size_t)l * NB * 1024, ph1c, nullptr, Msz, 1024, 512,
                nullptr, nullptr, nullptr, ptc, j);
            mma_gemm<GEPI_BLOCK, false><<<gN4, 256, MMA_SMEM_BYTES, s_sA>>>(
                ph1c, nullptr, pcw2T + (size_t)l * NB * 512 * 1024,
                cb2 + (size_t)l * NB * 512, pc, cmir, Msz, 512, 1024,
                cg + (size_t)l * NB * Dsz, tors, pmb, ptc, j);
        }
        // stream B: brainstem pathway
        for (int j = 0; j < 2; j++) {
            ln_kernel<<<Msz / 8, 256, 0, s_sB>>>(pb, pxnb, blng + (size_t)l * NB * Dsz,
                                                 blnb + (size_t)l * NB * Dsz, ptb, j);
            mma_gemm<GEPI_TANH, false><<<gN4, 256, MMA_SMEM_BYTES, s_sB>>>(
                pxnb, nullptr, pbw1T + (size_t)l * NB * 512 * 512,
                bb1 + (size_t)l * NB * 512, ph1b, nullptr, Msz, 512, 512,
                nullptr, nullptr, nullptr, ptb, j);
            mma_gemm<GEPI_BLOCK, false><<<gN4, 256, MMA_SMEM_BYTES, s_sB>>>(
                ph1b, nullptr, pbw2T + (size_t)l * NB * 512 * 512,
                bb2 + (size_t)l * NB * 512, pb, bmir, Msz, 512, 512,
                bg + (size_t)l * NB * Dsz, tors, pmc, ptb, j);
        }

        if (l == LNUM - 1) {
            // overlap final state copies with the join
            cudaMemcpyAsync(out,       pc, (size_t)BSD * 4, cudaMemcpyDeviceToDevice, s_sA);
            cudaMemcpyAsync(out + BSD, pb, (size_t)BSD * 4, cudaMemcpyDeviceToDevice, s_sB);
        }
        // join
        cudaEventRecord(s_eA, s_sA);
        cudaEventRecord(s_eB, s_sB);
        cudaStreamWaitEvent(0, s_eA, 0);
        cudaStreamWaitEvent(0, s_eB, 0);
    }

    // fused = concat([c, b], -1) @ w_cross[3] + b_cross[3], from half mirrors
    mma_gemm<GEPI_BIAS, true><<<gN4, 256, MMA_SMEM_BYTES>>>(
        pcm, pbm, pwcrT, bcr + (size_t)3 * Dsz,
        out + 2 * (size_t)BSD, nullptr, Msz, 512, 1024,
        nullptr, nullptr, nullptr, nullptr, 0);
}

// round 6
// speedup vs baseline: 5.4340x; 1.1281x over previous
#include <cuda_runtime.h>
#include <cuda_fp16.h>
#include <math.h>
#include <stdint.h>

// Problem constants
#define LNUM 4
#define NB   8
#define Bsz  16
#define Ssz  512
#define Dsz  512
#define Msz  (Bsz * Ssz)          // 8192
#define BSD  (Bsz * Ssz * Dsz)

// ---------------- device scratch ----------------
__device__ float  g_c[BSD];
__device__ float  g_b[BSD];
__device__ __half g_xnh_c[BSD];
__device__ __half g_xnh_b[BSD];
__device__ __half g_h1h_c[Bsz * Ssz * 2 * Dsz];
__device__ __half g_h1h_b[BSD];
__device__ __half g_cmir[BSD];
__device__ __half g_bmir[BSD];
__device__ float  g_mean_c[Bsz * Dsz];
__device__ float  g_mean_b[Bsz * Dsz];
__device__ int    g_top_c[2];
__device__ int    g_top_b[2];
__device__ __half g_cw1T[4 * 8 * 1024 * 512];
__device__ __half g_cw2T[4 * 8 * 512 * 1024];
__device__ __half g_bw1T[4 * 8 * 512 * 512];
__device__ __half g_bw2T[4 * 8 * 512 * 512];
__device__ __half g_wcrT[512 * 1024];

// ---------------- helpers ----------------
__device__ __forceinline__ uint32_t smem_u32(const void* p) {
    uint32_t a;
    asm("{ .reg .u64 t; cvta.to.shared.u64 t, %1; cvt.u32.u64 %0, t; }" : "=r"(a) : "l"(p));
    return a;
}
__device__ __forceinline__ void cp_async16(uint32_t saddr, const void* gaddr) {
    asm volatile("cp.async.cg.shared.global [%0], [%1], 16;" :: "r"(saddr), "l"(gaddr) : "memory");
}
__device__ __forceinline__ void cp_commit() {
    asm volatile("cp.async.commit_group;" ::: "memory");
}
template <int N>
__device__ __forceinline__ void cp_wait() {
    asm volatile("cp.async.wait_group %0;" :: "n"(N) : "memory");
}
__device__ __forceinline__ void ldm_x4(uint32_t* r, uint32_t addr) {
    asm volatile("ldmatrix.sync.aligned.m8n8.x4.shared.b16 {%0,%1,%2,%3}, [%4];"
        : "=r"(r[0]), "=r"(r[1]), "=r"(r[2]), "=r"(r[3]) : "r"(addr));
}
__device__ __forceinline__ void mma_f16(float* c, const uint32_t* a, const uint32_t* b) {
    asm volatile(
        "mma.sync.aligned.m16n8k16.row.col.f32.f16.f16.f32 "
        "{%0,%1,%2,%3}, {%4,%5,%6,%7}, {%8,%9}, {%0,%1,%2,%3};"
        : "+f"(c[0]), "+f"(c[1]), "+f"(c[2]), "+f"(c[3])
        : "r"(a[0]), "r"(a[1]), "r"(a[2]), "r"(a[3]), "r"(b[0]), "r"(b[1]));
}
__device__ __forceinline__ float warp_sum(float v) {
#pragma unroll
    for (int o = 16; o > 0; o >>= 1) v += __shfl_xor_sync(0xffffffffu, v, o);
    return v;
}

// ---------------- fused small kernels ----------------
__global__ void colmean_both_kernel(const float* __restrict__ xc, const float* __restrict__ xb,
                                    float* __restrict__ oc, float* __restrict__ ob) {
    const float* x = blockIdx.z ? xb : xc;
    float* o = blockIdx.z ? ob : oc;
    int b = blockIdx.x;
    int d = blockIdx.y * 256 + threadIdx.x;
    const float* p = x + (size_t)b * Ssz * Dsz + d;
    float s = 0.f;
#pragma unroll 8
    for (int t = 0; t < Ssz; t++) s += p[(size_t)t * Dsz];
    o[b * Dsz + d] = s * (1.0f / Ssz);
}

__global__ void route_both_kernel(const float* __restrict__ mc, const float* __restrict__ mb,
                                  const float* __restrict__ wc, const float* __restrict__ bc,
                                  const float* __restrict__ wb, const float* __restrict__ bbv,
                                  int* __restrict__ tc, int* __restrict__ tb) {
    const float* mean0 = blockIdx.x ? mb : mc;
    const float* wsel  = blockIdx.x ? wb : wc;
    const float* bsel  = blockIdx.x ? bbv : bc;
    int* top           = blockIdx.x ? tb : tc;
    int lane = threadIdx.x & 31, w = threadIdx.x >> 5;
    float s = 0.f;
    for (int d = lane; d < Dsz; d += 32) s += mean0[d] * wsel[d * NB + w];
#pragma unroll
    for (int o = 16; o > 0; o >>= 1) s += __shfl_down_sync(0xffffffffu, s, o);
    __shared__ float adj[NB];
    if (lane == 0) {
        float sc = 1.f / (1.f + expf(-(s + bsel[w])));
        adj[w] = sc * 0.7f + 0.15f;
    }
    __syncthreads();
    if (threadIdx.x == 0) {
        int i1 = 0; float v1 = adj[0];
        for (int n = 1; n < NB; n++) if (adj[n] > v1) { v1 = adj[n]; i1 = n; }
        int i2 = -1; float v2 = -1e30f;
        for (int n = 0; n < NB; n++) if (n != i1 && adj[n] > v2) { v2 = adj[n]; i2 = n; }
        top[0] = i1; top[1] = i2;
    }
}

__global__ void ln_kernel(const float* __restrict__ x, __half* __restrict__ xn,
                          const float* __restrict__ lng, const float* __restrict__ lnb,
                          const int* __restrict__ top, int jsel) {
    int i = top[jsel];
    int row = blockIdx.x * 8 + (threadIdx.x >> 5);
    int lane = threadIdx.x & 31;
    const float4* xr = (const float4*)(x + (size_t)row * Dsz);
    float4 v[4];
    float s = 0.f;
#pragma unroll
    for (int q = 0; q < 4; q++) {
        v[q] = xr[lane + q * 32];
        s += v[q].x + v[q].y + v[q].z + v[q].w;
    }
    float mu = warp_sum(s) * (1.f / Dsz);
    float ss = 0.f;
#pragma unroll
    for (int q = 0; q < 4; q++) {
        float a = v[q].x - mu, b = v[q].y - mu, c = v[q].z - mu, d = v[q].w - mu;
        ss += a * a + b * b + c * c + d * d;
    }
    float r = rsqrtf(warp_sum(ss) * (1.f / Dsz) + 1e-5f);
    const float4* gg = (const float4*)(lng + (size_t)i * Dsz);
    const float4* bb = (const float4*)(lnb + (size_t)i * Dsz);
#pragma unroll
    for (int q = 0; q < 4; q++) {
        int c4 = lane + q * 32;
        float4 g = gg[c4], be = bb[c4];
        float o0 = (v[q].x - mu) * r * g.x + be.x;
        float o1 = (v[q].y - mu) * r * g.y + be.y;
        float o2 = (v[q].z - mu) * r * g.z + be.z;
        float o3 = (v[q].w - mu) * r * g.w + be.w;
        __half2 h0 = __floats2half2_rn(o0, o1);
        __half2 h1 = __floats2half2_rn(o2, o3);
        uint2 pk = make_uint2(*(uint32_t*)&h0, *(uint32_t*)&h1);
        *(uint2*)(xn + (size_t)row * Dsz + c4 * 4) = pk;
    }
}

__global__ void transpose_h_kernel(const float* __restrict__ W, __half* __restrict__ WT,
                                   int K, int N) {
    __shared__ float tile[32][33];
    const float* Wz = W + (size_t)blockIdx.z * K * N;
    __half* Tz = WT + (size_t)blockIdx.z * K * N;
    int x = blockIdx.x * 32 + threadIdx.x;
    int y0 = blockIdx.y * 32;
#pragma unroll
    for (int j = 0; j < 4; j++)
        tile[threadIdx.y + j * 8][threadIdx.x] = Wz[(size_t)(y0 + threadIdx.y + j * 8) * N + x];
    __syncthreads();
    int x2 = blockIdx.y * 32 + threadIdx.x;
    int y2 = blockIdx.x * 32;
#pragma unroll
    for (int j = 0; j < 4; j++)
        Tz[(size_t)(y2 + threadIdx.y + j * 8) * K + x2] = __float2half_rn(tile[threadIdx.x][threadIdx.y + j * 8]);
}

// ---------------- fp16 mma.sync GEMM: 128x128 tile, BK=32, 3-stage cp.async, ldmatrix ----------------
#define GEPI_GELU  0
#define GEPI_TANH  1
#define GEPI_BLOCK 2
#define GEPI_BIAS  3

#define KPADH 40
#define TILEH (128 * KPADH)
#define NSTAGE 3
#define MMA_SMEM_BYTES (NSTAGE * 2 * TILEH * 2)   // 61440 B

template <int EPI, bool CONCAT>
__global__ void __launch_bounds__(256, 2) mma_gemm(
    const __half* __restrict__ A, const __half* __restrict__ A2,
    const __half* __restrict__ BT, const float* __restrict__ bias,
    void* __restrict__ Cv, __half* __restrict__ mirror, int M, int N, int K,
    const float* __restrict__ gate, const float* __restrict__ torsion,
    const float* __restrict__ meanOther,
    const int* __restrict__ top, int jsel)
{
    extern __shared__ __half smh[];

    int tid = threadIdx.x;
    int wid = tid >> 5, lane = tid & 31;
    int g = lane >> 2, t = lane & 3;
    int lr = lane & 7, seg = lane >> 3;
    int wm = wid & 3, wn = wid >> 2;            // 4x2 warps; warp tile 32(m) x 64(n)
    int bm = blockIdx.y * 128;
    int bn = blockIdx.x * 128;

    int ii = 0;
    if (top) ii = top[jsel];
    const __half* Bp  = BT + (size_t)ii * K * N + (size_t)bn * K;
    const float*  bia = bias + (size_t)ii * N;

    uint32_t sbase = smem_u32(smh);

    auto load_tile = [&](int c) {
        int st = c % NSTAGE;
        int k0 = c << 5;
        uint32_t sAa = sbase + (uint32_t)(st * 2 * TILEH) * 2;
        uint32_t sBa = sAa + (uint32_t)TILEH * 2;
#pragma unroll
        for (int i = 0; i < 2; i++) {
            int idx = i * 256 + tid;
            int row = idx >> 2;
            int ch  = (idx & 3) * 8;
            const __half* gsrc;
            if (CONCAT) {
                int kk = k0 + ch;
                gsrc = (kk < 512) ? (A + (size_t)(bm + row) * 512 + kk)
                                  : (A2 + (size_t)(bm + row) * 512 + (kk - 512));
            } else {
                gsrc = A + (size_t)(bm + row) * K + k0 + ch;
            }
            cp_async16(sAa + (uint32_t)(row * KPADH + ch) * 2, gsrc);
            cp_async16(sBa + (uint32_t)(row * KPADH + ch) * 2, Bp + (size_t)row * K + k0 + ch);
        }
        cp_commit();
    };

    float acc[2][8][4];
#pragma unroll
    for (int a = 0; a < 2; a++)
#pragma unroll
        for (int b = 0; b < 8; b++)
#pragma unroll
            for (int q = 0; q < 4; q++) acc[a][b][q] = 0.f;

    const int nk = K >> 5;
    load_tile(0);
    load_tile(1);

    // ldmatrix address components (lane-dependent, stage-independent parts)
    int a_row = wm * 32 + (seg & 1) * 8 + lr;    // + mt*16
    int a_col = (seg >> 1) * 8;                  // + s*16
    int b_row = wn * 64 + (seg >> 1) * 8 + lr;   // + pair*16
    int b_col = (seg & 1) * 8;                   // + s*16

    for (int c = 0; c < nk; c++) {
        if (c + 2 < nk)      { load_tile(c + 2); cp_wait<2>(); }
        else if (c + 1 < nk) { cp_wait<1>(); }
        else                 { cp_wait<0>(); }
        __syncthreads();

        uint32_t aBase = sbase + (uint32_t)((c % NSTAGE) * 2 * TILEH) * 2;
        uint32_t bBase = aBase + (uint32_t)TILEH * 2;

#pragma unroll
        for (int s = 0; s < 2; s++) {
            uint32_t af[2][4], bf[8][2];
#pragma unroll
            for (int mt = 0; mt < 2; mt++)
                ldm_x4(af[mt], aBase + (uint32_t)((a_row + mt * 16) * KPADH + a_col + s * 16) * 2);
#pragma unroll
            for (int p = 0; p < 4; p++) {
                uint32_t r[4];
                ldm_x4(r, bBase + (uint32_t)((b_row + p * 16) * KPADH + b_col + s * 16) * 2);
                bf[2 * p][0]     = r[0];
                bf[2 * p][1]     = r[1];
                bf[2 * p + 1][0] = r[2];
                bf[2 * p + 1][1] = r[3];
            }
#pragma unroll
            for (int mt = 0; mt < 2; mt++)
#pragma unroll
                for (int nt = 0; nt < 8; nt++)
                    mma_f16(acc[mt][nt], af[mt], bf[nt]);
        }
        __syncthreads();
    }

    // ---------------- epilogue ----------------
#pragma unroll
    for (int mt = 0; mt < 2; mt++) {
        int m0 = bm + wm * 32 + mt * 16 + g;
#pragma unroll
        for (int half = 0; half < 2; half++) {
            int m = m0 + half * 8;
            int batch = m >> 9;
#pragma unroll
            for (int nt = 0; nt < 8; nt++) {
                int n = bn + wn * 64 + nt * 8 + t * 2;
                float v0 = acc[mt][nt][half * 2 + 0] + bia[n];
                float v1 = acc[mt][nt][half * 2 + 1] + bia[n + 1];
                if (EPI == GEPI_GELU) {
                    float o0 = v0 * 0.5f * (1.0f + erff(v0 * 0.7071067811865475f));
                    float o1 = v1 * 0.5f * (1.0f + erff(v1 * 0.7071067811865475f));
                    *(__half2*)((__half*)Cv + (size_t)m * N + n) = __floats2half2_rn(o0, o1);
                } else if (EPI == GEPI_TANH) {
                    *(__half2*)((__half*)Cv + (size_t)m * N + n) = __floats2half2_rn(tanhf(v0), tanhf(v1));
                } else if (EPI == GEPI_BIAS) {
                    *(float2*)((float*)Cv + (size_t)m * N + n) = make_float2(v0, v1);
                } else {
                    float* C = (float*)Cv;
                    const float* gp = gate + (size_t)ii * N;
                    float tg0 = 1.f / (1.f + expf(-gp[n]));
                    float tg1 = 1.f / (1.f + expf(-gp[n + 1]));
                    float s0 = meanOther[(size_t)batch * Dsz + n] * 0.3f;
                    float s1 = meanOther[(size_t)batch * Dsz + n + 1] * 0.3f;
                    float h0 = v0 * (1.f + tg0 * torsion[n])     + s0 * tg0;
                    float h1 = v1 * (1.f + tg1 * torsion[n + 1]) + s1 * tg1;
                    float2 old = *(const float2*)(C + (size_t)m * N + n);
                    float o0 = old.x + 0.5f * h0, o1 = old.y + 0.5f * h1;
                    *(float2*)(C + (size_t)m * N + n) = make_float2(o0, o1);
                    if (mirror)
                        *(__half2*)(mirror + (size_t)m * N + n) = __floats2half2_rn(o0, o1);
                }
            }
        }
    }
}

// ---------------- host orchestration ----------------
static cudaStream_t s_sA = nullptr, s_sB = nullptr;
static cudaEvent_t  s_eF = nullptr, s_eA = nullptr, s_eB = nullptr;
static void ensure_streams() {
    if (!s_sA) {
        cudaStreamCreateWithFlags(&s_sA, cudaStreamNonBlocking);
        cudaStreamCreateWithFlags(&s_sB, cudaStreamNonBlocking);
        cudaEventCreateWithFlags(&s_eF, cudaEventDisableTiming);
        cudaEventCreateWithFlags(&s_eA, cudaEventDisableTiming);
        cudaEventCreateWithFlags(&s_eB, cudaEventDisableTiming);
    }
}

extern "C" void kernel_launch(void* const* d_in, const int* in_sizes, int n_in,
                              void* d_out, int out_size) {
    const float* in_c   = (const float*)d_in[0];
    const float* in_b   = (const float*)d_in[1];
    const float* tors   = (const float*)d_in[2];
    const float* wsel_c = (const float*)d_in[3];
    const float* bsel_c = (const float*)d_in[4];
    const float* wsel_b = (const float*)d_in[5];
    const float* bsel_b = (const float*)d_in[6];
    const float* clng   = (const float*)d_in[7];
    const float* clnb   = (const float*)d_in[8];
    const float* cw1    = (const float*)d_in[9];
    const float* cb1    = (const float*)d_in[10];
    const float* cw2    = (const float*)d_in[11];
    const float* cb2    = (const float*)d_in[12];
    const float* cg     = (const float*)d_in[13];
    const float* blng   = (const float*)d_in[14];
    const float* blnb   = (const float*)d_in[15];
    const float* bw1    = (const float*)d_in[16];
    const float* bb1    = (const float*)d_in[17];
    const float* bw2    = (const float*)d_in[18];
    const float* bb2    = (const float*)d_in[19];
    const float* bg     = (const float*)d_in[20];
    const float* wcr    = (const float*)d_in[21];
    const float* bcr    = (const float*)d_in[22];
    float* out = (float*)d_out;

    ensure_streams();

    float *pc, *pb, *pmc, *pmb;
    __half *pxnc, *pxnb, *ph1c, *ph1b, *pcm, *pbm;
    __half *pcw1T, *pcw2T, *pbw1T, *pbw2T, *pwcrT;
    int *ptc, *ptb;
    cudaGetSymbolAddress((void**)&pc,   g_c);
    cudaGetSymbolAddress((void**)&pb,   g_b);
    cudaGetSymbolAddress((void**)&pxnc, g_xnh_c);
    cudaGetSymbolAddress((void**)&pxnb, g_xnh_b);
    cudaGetSymbolAddress((void**)&ph1c, g_h1h_c);
    cudaGetSymbolAddress((void**)&ph1b, g_h1h_b);
    cudaGetSymbolAddress((void**)&pcm,  g_cmir);
    cudaGetSymbolAddress((void**)&pbm,  g_bmir);
    cudaGetSymbolAddress((void**)&pmc,  g_mean_c);
    cudaGetSymbolAddress((void**)&pmb,  g_mean_b);
    cudaGetSymbolAddress((void**)&ptc,  g_top_c);
    cudaGetSymbolAddress((void**)&ptb,  g_top_b);
    cudaGetSymbolAddress((void**)&pcw1T, g_cw1T);
    cudaGetSymbolAddress((void**)&pcw2T, g_cw2T);
    cudaGetSymbolAddress((void**)&pbw1T, g_bw1T);
    cudaGetSymbolAddress((void**)&pbw2T, g_bw2T);
    cudaGetSymbolAddress((void**)&pwcrT, g_wcrT);

    cudaFuncSetAttribute(mma_gemm<GEPI_GELU,  false>, cudaFuncAttributeMaxDynamicSharedMemorySize, MMA_SMEM_BYTES);
    cudaFuncSetAttribute(mma_gemm<GEPI_TANH,  false>, cudaFuncAttributeMaxDynamicSharedMemorySize, MMA_SMEM_BYTES);
    cudaFuncSetAttribute(mma_gemm<GEPI_BLOCK, false>, cudaFuncAttributeMaxDynamicSharedMemorySize, MMA_SMEM_BYTES);
    cudaFuncSetAttribute(mma_gemm<GEPI_BIAS,  true >, cudaFuncAttributeMaxDynamicSharedMemorySize, MMA_SMEM_BYTES);

    dim3 tb(32, 8);
    dim3 gN4(4, Msz / 128);
    dim3 gN8(8, Msz / 128);

    // ---- prologue: input copies + ALL weight transposes ----
    cudaMemcpyAsync(pc, in_c, (size_t)BSD * 4, cudaMemcpyDeviceToDevice, 0);
    cudaMemcpyAsync(pb, in_b, (size_t)BSD * 4, cudaMemcpyDeviceToDevice, 0);
    transpose_h_kernel<<<dim3(32, 16, 32), tb>>>(cw1, pcw1T, 512, 1024);
    transpose_h_kernel<<<dim3(16, 32, 32), tb>>>(cw2, pcw2T, 1024, 512);
    transpose_h_kernel<<<dim3(16, 16, 32), tb>>>(bw1, pbw1T, 512, 512);
    transpose_h_kernel<<<dim3(16, 16, 32), tb>>>(bw2, pbw2T, 512, 512);
    transpose_h_kernel<<<dim3(16, 32, 1),  tb>>>(wcr + (size_t)3 * 1024 * 512, pwcrT, 1024, 512);

    for (int l = 0; l < LNUM; l++) {
        colmean_both_kernel<<<dim3(Bsz, 2, 2), 256>>>(pc, pb, pmc, pmb);
        route_both_kernel<<<2, 256>>>(pmc, pmb,
                                      wsel_c + (size_t)l * Dsz * NB, bsel_c + l * NB,
                                      wsel_b + (size_t)l * Dsz * NB, bsel_b + l * NB,
                                      ptc, ptb);
        cudaEventRecord(s_eF, 0);
        cudaStreamWaitEvent(s_sA, s_eF, 0);
        cudaStreamWaitEvent(s_sB, s_eF, 0);

        __half* cmir = (l == LNUM - 1) ? pcm : nullptr;
        __half* bmir = (l == LNUM - 1) ? pbm : nullptr;

        for (int j = 0; j < 2; j++) {
            ln_kernel<<<Msz / 8, 256, 0, s_sA>>>(pc, pxnc, clng + (size_t)l * NB * Dsz,
                                                 clnb + (size_t)l * NB * Dsz, ptc, j);
            mma_gemm<GEPI_GELU, false><<<gN8, 256, MMA_SMEM_BYTES, s_sA>>>(
                pxnc, nullptr, pcw1T + (size_t)l * NB * 1024 * 512,
                cb1 + (size_t)l * NB * 1024, ph1c, nullptr, Msz, 1024, 512,
                nullptr, nullptr, nullptr, ptc, j);
            mma_gemm<GEPI_BLOCK, false><<<gN4, 256, MMA_SMEM_BYTES, s_sA>>>(
                ph1c, nullptr, pcw2T + (size_t)l * NB * 512 * 1024,
                cb2 + (size_t)l * NB * 512, pc, cmir, Msz, 512, 1024,
                cg + (size_t)l * NB * Dsz, tors, pmb, ptc, j);
        }
        for (int j = 0; j < 2; j++) {
            ln_kernel<<<Msz / 8, 256, 0, s_sB>>>(pb, pxnb, blng + (size_t)l * NB * Dsz,
                                                 blnb + (size_t)l * NB * Dsz, ptb, j);
            mma_gemm<GEPI_TANH, false><<<gN4, 256, MMA_SMEM_BYTES, s_sB>>>(
                pxnb, nullptr, pbw1T + (size_t)l * NB * 512 * 512,
                bb1 + (size_t)l * NB * 512, ph1b, nullptr, Msz, 512, 512,
                nullptr, nullptr, nullptr, ptb, j);
            mma_gemm<GEPI_BLOCK, false><<<gN4, 256, MMA_SMEM_BYTES, s_sB>>>(
                ph1b, nullptr, pbw2T + (size_t)l * NB * 512 * 512,
                bb2 + (size_t)l * NB * 512, pb, bmir, Msz, 512, 512,
                bg + (size_t)l * NB * Dsz, tors, pmc, ptb, j);
        }

        if (l == LNUM - 1) {
            cudaMemcpyAsync(out,       pc, (size_t)BSD * 4, cudaMemcpyDeviceToDevice, s_sA);
            cudaMemcpyAsync(out + BSD, pb, (size_t)BSD * 4, cudaMemcpyDeviceToDevice, s_sB);
        }
        cudaEventRecord(s_eA, s_sA);
        cudaEventRecord(s_eB, s_sB);
        cudaStreamWaitEvent(0, s_eA, 0);
        cudaStreamWaitEvent(0, s_eB, 0);
    }

    mma_gemm<GEPI_BIAS, true><<<gN4, 256, MMA_SMEM_BYTES>>>(
        pcm, pbm, pwcrT, bcr + (size_t)3 * Dsz,
        out + 2 * (size_t)BSD, nullptr, Msz, 512, 1024,
        nullptr, nullptr, nullptr, nullptr, 0);
}

// round 7
// speedup vs baseline: 6.2114x; 1.1431x over previous
#include <cuda_runtime.h>
#include <cuda_fp16.h>
#include <math.h>
#include <stdint.h>

// Problem constants
#define LNUM 4
#define NB   8
#define Bsz  16
#define Ssz  512
#define Dsz  512
#define Msz  (Bsz * Ssz)          // 8192
#define BSD  (Bsz * Ssz * Dsz)

// ---------------- device scratch ----------------
__device__ float  g_c[BSD];
__device__ float  g_b[BSD];
__device__ __half g_xnh_c[BSD];
__device__ __half g_xnh_b[BSD];
__device__ __half g_h1h_c[Bsz * Ssz * 2 * Dsz];
__device__ __half g_h1h_b[BSD];
__device__ __half g_cmir[BSD];
__device__ __half g_bmir[BSD];
__device__ float  g_mean_c[2 * Bsz * Dsz];   // double-buffered by layer parity
__device__ float  g_mean_b[2 * Bsz * Dsz];
__device__ int    g_top_c[2];
__device__ int    g_top_b[2];
__device__ __half g_cw1T[4 * 8 * 1024 * 512];
__device__ __half g_cw2T[4 * 8 * 512 * 1024];
__device__ __half g_bw1T[4 * 8 * 512 * 512];
__device__ __half g_bw2T[4 * 8 * 512 * 512];
__device__ __half g_wcrT[512 * 1024];

// ---------------- helpers ----------------
__device__ __forceinline__ uint32_t smem_u32(const void* p) {
    uint32_t a;
    asm("{ .reg .u64 t; cvta.to.shared.u64 t, %1; cvt.u32.u64 %0, t; }" : "=r"(a) : "l"(p));
    return a;
}
__device__ __forceinline__ void cp_async16(uint32_t saddr, const void* gaddr) {
    asm volatile("cp.async.cg.shared.global [%0], [%1], 16;" :: "r"(saddr), "l"(gaddr) : "memory");
}
__device__ __forceinline__ void cp_commit() {
    asm volatile("cp.async.commit_group;" ::: "memory");
}
template <int N>
__device__ __forceinline__ void cp_wait() {
    asm volatile("cp.async.wait_group %0;" :: "n"(N) : "memory");
}
__device__ __forceinline__ void ldm_x4(uint32_t* r, uint32_t addr) {
    asm volatile("ldmatrix.sync.aligned.m8n8.x4.shared.b16 {%0,%1,%2,%3}, [%4];"
        : "=r"(r[0]), "=r"(r[1]), "=r"(r[2]), "=r"(r[3]) : "r"(addr));
}
__device__ __forceinline__ void mma_f16(float* c, const uint32_t* a, const uint32_t* b) {
    asm volatile(
        "mma.sync.aligned.m16n8k16.row.col.f32.f16.f16.f32 "
        "{%0,%1,%2,%3}, {%4,%5,%6,%7}, {%8,%9}, {%0,%1,%2,%3};"
        : "+f"(c[0]), "+f"(c[1]), "+f"(c[2]), "+f"(c[3])
        : "r"(a[0]), "r"(a[1]), "r"(a[2]), "r"(a[3]), "r"(b[0]), "r"(b[1]));
}
__device__ __forceinline__ float warp_sum(float v) {
#pragma unroll
    for (int o = 16; o > 0; o >>= 1) v += __shfl_xor_sync(0xffffffffu, v, o);
    return v;
}

// ---------------- small kernels (per-stream versions) ----------------
__global__ void colmean_kernel(const float* __restrict__ x, float* __restrict__ out) {
    int b = blockIdx.x;
    int d = blockIdx.y * 256 + threadIdx.x;
    const float* p = x + (size_t)b * Ssz * Dsz + d;
    float s = 0.f;
#pragma unroll 8
    for (int t = 0; t < Ssz; t++) s += p[(size_t)t * Dsz];
    out[b * Dsz + d] = s * (1.0f / Ssz);
}

__global__ void route_kernel(const float* __restrict__ mean0, const float* __restrict__ wsel,
                             const float* __restrict__ bsel, int* __restrict__ top) {
    int lane = threadIdx.x & 31, w = threadIdx.x >> 5;
    float s = 0.f;
    for (int d = lane; d < Dsz; d += 32) s += mean0[d] * wsel[d * NB + w];
#pragma unroll
    for (int o = 16; o > 0; o >>= 1) s += __shfl_down_sync(0xffffffffu, s, o);
    __shared__ float adj[NB];
    if (lane == 0) {
        float sc = 1.f / (1.f + expf(-(s + bsel[w])));
        adj[w] = sc * 0.7f + 0.15f;
    }
    __syncthreads();
    if (threadIdx.x == 0) {
        int i1 = 0; float v1 = adj[0];
        for (int n = 1; n < NB; n++) if (adj[n] > v1) { v1 = adj[n]; i1 = n; }
        int i2 = -1; float v2 = -1e30f;
        for (int n = 0; n < NB; n++) if (n != i1 && adj[n] > v2) { v2 = adj[n]; i2 = n; }
        top[0] = i1; top[1] = i2;
    }
}

__global__ void ln_kernel(const float* __restrict__ x, __half* __restrict__ xn,
                          const float* __restrict__ lng, const float* __restrict__ lnb,
                          const int* __restrict__ top, int jsel) {
    int i = top[jsel];
    int row = blockIdx.x * 8 + (threadIdx.x >> 5);
    int lane = threadIdx.x & 31;
    const float4* xr = (const float4*)(x + (size_t)row * Dsz);
    float4 v[4];
    float s = 0.f;
#pragma unroll
    for (int q = 0; q < 4; q++) {
        v[q] = xr[lane + q * 32];
        s += v[q].x + v[q].y + v[q].z + v[q].w;
    }
    float mu = warp_sum(s) * (1.f / Dsz);
    float ss = 0.f;
#pragma unroll
    for (int q = 0; q < 4; q++) {
        float a = v[q].x - mu, b = v[q].y - mu, c = v[q].z - mu, d = v[q].w - mu;
        ss += a * a + b * b + c * c + d * d;
    }
    float r = rsqrtf(warp_sum(ss) * (1.f / Dsz) + 1e-5f);
    const float4* gg = (const float4*)(lng + (size_t)i * Dsz);
    const float4* bb = (const float4*)(lnb + (size_t)i * Dsz);
#pragma unroll
    for (int q = 0; q < 4; q++) {
        int c4 = lane + q * 32;
        float4 g = gg[c4], be = bb[c4];
        float o0 = (v[q].x - mu) * r * g.x + be.x;
        float o1 = (v[q].y - mu) * r * g.y + be.y;
        float o2 = (v[q].z - mu) * r * g.z + be.z;
        float o3 = (v[q].w - mu) * r * g.w + be.w;
        __half2 h0 = __floats2half2_rn(o0, o1);
        __half2 h1 = __floats2half2_rn(o2, o3);
        uint2 pk = make_uint2(*(uint32_t*)&h0, *(uint32_t*)&h1);
        *(uint2*)(xn + (size_t)row * Dsz + c4 * 4) = pk;
    }
}

// W [K,N] fp32 -> WT [N,K] half; z selects routed block via top (or direct when top==null)
__global__ void transpose_h_kernel(const float* __restrict__ W, __half* __restrict__ WT,
                                   int K, int N, const int* __restrict__ top) {
    __shared__ float tile[32][33];
    int ii = top ? top[blockIdx.z] : (int)blockIdx.z;
    const float* Wz = W + (size_t)ii * K * N;
    __half* Tz = WT + (size_t)ii * K * N;
    int x = blockIdx.x * 32 + threadIdx.x;
    int y0 = blockIdx.y * 32;
#pragma unroll
    for (int j = 0; j < 4; j++)
        tile[threadIdx.y + j * 8][threadIdx.x] = Wz[(size_t)(y0 + threadIdx.y + j * 8) * N + x];
    __syncthreads();
    int x2 = blockIdx.y * 32 + threadIdx.x;
    int y2 = blockIdx.x * 32;
#pragma unroll
    for (int j = 0; j < 4; j++)
        Tz[(size_t)(y2 + threadIdx.y + j * 8) * K + x2] = __float2half_rn(tile[threadIdx.x][threadIdx.y + j * 8]);
}

// ---------------- fp16 mma.sync GEMM: 128x128 tile, BK=64, 3-stage cp.async, ldmatrix ----------------
#define GEPI_GELU  0
#define GEPI_TANH  1
#define GEPI_BLOCK 2
#define GEPI_BIAS  3

#define KPADH 72
#define TILEH (128 * KPADH)
#define NSTAGE 3
#define MMA_SMEM_BYTES (NSTAGE * 2 * TILEH * 2)   // 110592 B

template <int EPI, bool CONCAT>
__global__ void __launch_bounds__(256, 2) mma_gemm(
    const __half* __restrict__ A, const __half* __restrict__ A2,
    const __half* __restrict__ BT, const float* __restrict__ bias,
    void* __restrict__ Cv, __half* __restrict__ mirror, int M, int N, int K,
    const float* __restrict__ gate, const float* __restrict__ torsion,
    const float* __restrict__ meanOther,
    const int* __restrict__ top, int jsel)
{
    extern __shared__ __half smh[];

    int tid = threadIdx.x;
    int wid = tid >> 5, lane = tid & 31;
    int g = lane >> 2, t = lane & 3;
    int lr = lane & 7, seg = lane >> 3;
    int wm = wid & 3, wn = wid >> 2;
    int bm = blockIdx.y * 128;
    int bn = blockIdx.x * 128;

    int ii = 0;
    if (top) ii = top[jsel];
    const __half* Bp  = BT + (size_t)ii * K * N + (size_t)bn * K;
    const float*  bia = bias + (size_t)ii * N;

    uint32_t sbase = smem_u32(smh);

    auto load_tile = [&](int c) {
        int st = c % NSTAGE;
        int k0 = c << 6;
        uint32_t sAa = sbase + (uint32_t)(st * 2 * TILEH) * 2;
        uint32_t sBa = sAa + (uint32_t)TILEH * 2;
#pragma unroll
        for (int i = 0; i < 4; i++) {
            int idx = i * 256 + tid;          // 0..1023
            int row = idx >> 3;               // 0..127
            int ch  = (idx & 7) * 8;          // 0..56
            const __half* gsrc;
            if (CONCAT) {
                int kk = k0 + ch;
                gsrc = (kk < 512) ? (A + (size_t)(bm + row) * 512 + kk)
                                  : (A2 + (size_t)(bm + row) * 512 + (kk - 512));
            } else {
                gsrc = A + (size_t)(bm + row) * K + k0 + ch;
            }
            cp_async16(sAa + (uint32_t)(row * KPADH + ch) * 2, gsrc);
            cp_async16(sBa + (uint32_t)(row * KPADH + ch) * 2, Bp + (size_t)row * K + k0 + ch);
        }
        cp_commit();
    };

    float acc[2][8][4];
#pragma unroll
    for (int a = 0; a < 2; a++)
#pragma unroll
        for (int b = 0; b < 8; b++)
#pragma unroll
            for (int q = 0; q < 4; q++) acc[a][b][q] = 0.f;

    const int nk = K >> 6;
    load_tile(0);
    load_tile(1);

    int a_row = wm * 32 + (seg & 1) * 8 + lr;
    int a_col = (seg >> 1) * 8;
    int b_row = wn * 64 + (seg >> 1) * 8 + lr;
    int b_col = (seg & 1) * 8;

    for (int c = 0; c < nk; c++) {
        if (c + 2 < nk)      { load_tile(c + 2); cp_wait<2>(); }
        else if (c + 1 < nk) { cp_wait<1>(); }
        else                 { cp_wait<0>(); }
        __syncthreads();

        uint32_t aBase = sbase + (uint32_t)((c % NSTAGE) * 2 * TILEH) * 2;
        uint32_t bBase = aBase + (uint32_t)TILEH * 2;

#pragma unroll
        for (int s = 0; s < 4; s++) {
            uint32_t af[2][4], bf[8][2];
#pragma unroll
            for (int mt = 0; mt < 2; mt++)
                ldm_x4(af[mt], aBase + (uint32_t)((a_row + mt * 16) * KPADH + a_col + s * 16) * 2);
#pragma unroll
            for (int p = 0; p < 4; p++) {
                uint32_t r[4];
                ldm_x4(r, bBase + (uint32_t)((b_row + p * 16) * KPADH + b_col + s * 16) * 2);
                bf[2 * p][0]     = r[0];
                bf[2 * p][1]     = r[1];
                bf[2 * p + 1][0] = r[2];
                bf[2 * p + 1][1] = r[3];
            }
#pragma unroll
            for (int mt = 0; mt < 2; mt++)
#pragma unroll
                for (int nt = 0; nt < 8; nt++)
                    mma_f16(acc[mt][nt], af[mt], bf[nt]);
        }
        __syncthreads();
    }

    // ---------------- epilogue ----------------
#pragma unroll
    for (int mt = 0; mt < 2; mt++) {
        int m0 = bm + wm * 32 + mt * 16 + g;
#pragma unroll
        for (int half = 0; half < 2; half++) {
            int m = m0 + half * 8;
            int batch = m >> 9;
#pragma unroll
            for (int nt = 0; nt < 8; nt++) {
                int n = bn + wn * 64 + nt * 8 + t * 2;
                float v0 = acc[mt][nt][half * 2 + 0] + bia[n];
                float v1 = acc[mt][nt][half * 2 + 1] + bia[n + 1];
                if (EPI == GEPI_GELU) {
                    float o0 = v0 * 0.5f * (1.0f + erff(v0 * 0.7071067811865475f));
                    float o1 = v1 * 0.5f * (1.0f + erff(v1 * 0.7071067811865475f));
                    *(__half2*)((__half*)Cv + (size_t)m * N + n) = __floats2half2_rn(o0, o1);
                } else if (EPI == GEPI_TANH) {
                    *(__half2*)((__half*)Cv + (size_t)m * N + n) = __floats2half2_rn(tanhf(v0), tanhf(v1));
                } else if (EPI == GEPI_BIAS) {
                    *(float2*)((float*)Cv + (size_t)m * N + n) = make_float2(v0, v1);
                } else {
                    float* C = (float*)Cv;
                    const float* gp = gate + (size_t)ii * N;
                    float tg0 = 1.f / (1.f + expf(-gp[n]));
                    float tg1 = 1.f / (1.f + expf(-gp[n + 1]));
                    float s0 = meanOther[(size_t)batch * Dsz + n] * 0.3f;
                    float s1 = meanOther[(size_t)batch * Dsz + n + 1] * 0.3f;
                    float h0 = v0 * (1.f + tg0 * torsion[n])     + s0 * tg0;
                    float h1 = v1 * (1.f + tg1 * torsion[n + 1]) + s1 * tg1;
                    float2 old = *(const float2*)(C + (size_t)m * N + n);
                    float o0 = old.x + 0.5f * h0, o1 = old.y + 0.5f * h1;
                    *(float2*)(C + (size_t)m * N + n) = make_float2(o0, o1);
                    if (mirror)
                        *(__half2*)(mirror + (size_t)m * N + n) = __floats2half2_rn(o0, o1);
                }
            }
        }
    }
}

// ---------------- host orchestration ----------------
static cudaStream_t s_sA = nullptr, s_sB = nullptr;
static cudaEvent_t  s_eF = nullptr, s_eAm = nullptr, s_eBm = nullptr, s_eAf = nullptr, s_eBf = nullptr;
static void ensure_streams() {
    if (!s_sA) {
        cudaStreamCreateWithFlags(&s_sA, cudaStreamNonBlocking);
        cudaStreamCreateWithFlags(&s_sB, cudaStreamNonBlocking);
        cudaEventCreateWithFlags(&s_eF,  cudaEventDisableTiming);
        cudaEventCreateWithFlags(&s_eAm, cudaEventDisableTiming);
        cudaEventCreateWithFlags(&s_eBm, cudaEventDisableTiming);
        cudaEventCreateWithFlags(&s_eAf, cudaEventDisableTiming);
        cudaEventCreateWithFlags(&s_eBf, cudaEventDisableTiming);
    }
}

extern "C" void kernel_launch(void* const* d_in, const int* in_sizes, int n_in,
                              void* d_out, int out_size) {
    const float* in_c   = (const float*)d_in[0];
    const float* in_b   = (const float*)d_in[1];
    const float* tors   = (const float*)d_in[2];
    const float* wsel_c = (const float*)d_in[3];
    const float* bsel_c = (const float*)d_in[4];
    const float* wsel_b = (const float*)d_in[5];
    const float* bsel_b = (const float*)d_in[6];
    const float* clng   = (const float*)d_in[7];
    const float* clnb   = (const float*)d_in[8];
    const float* cw1    = (const float*)d_in[9];
    const float* cb1    = (const float*)d_in[10];
    const float* cw2    = (const float*)d_in[11];
    const float* cb2    = (const float*)d_in[12];
    const float* cg     = (const float*)d_in[13];
    const float* blng   = (const float*)d_in[14];
    const float* blnb   = (const float*)d_in[15];
    const float* bw1    = (const float*)d_in[16];
    const float* bb1    = (const float*)d_in[17];
    const float* bw2    = (const float*)d_in[18];
    const float* bb2    = (const float*)d_in[19];
    const float* bg     = (const float*)d_in[20];
    const float* wcr    = (const float*)d_in[21];
    const float* bcr    = (const float*)d_in[22];
    float* out = (float*)d_out;

    ensure_streams();

    float *pc, *pb, *pmc, *pmb;
    __half *pxnc, *pxnb, *ph1c, *ph1b, *pcm, *pbm;
    __half *pcw1T, *pcw2T, *pbw1T, *pbw2T, *pwcrT;
    int *ptc, *ptb;
    cudaGetSymbolAddress((void**)&pc,   g_c);
    cudaGetSymbolAddress((void**)&pb,   g_b);
    cudaGetSymbolAddress((void**)&pxnc, g_xnh_c);
    cudaGetSymbolAddress((void**)&pxnb, g_xnh_b);
    cudaGetSymbolAddress((void**)&ph1c, g_h1h_c);
    cudaGetSymbolAddress((void**)&ph1b, g_h1h_b);
    cudaGetSymbolAddress((void**)&pcm,  g_cmir);
    cudaGetSymbolAddress((void**)&pbm,  g_bmir);
    cudaGetSymbolAddress((void**)&pmc,  g_mean_c);
    cudaGetSymbolAddress((void**)&pmb,  g_mean_b);
    cudaGetSymbolAddress((void**)&ptc,  g_top_c);
    cudaGetSymbolAddress((void**)&ptb,  g_top_b);
    cudaGetSymbolAddress((void**)&pcw1T, g_cw1T);
    cudaGetSymbolAddress((void**)&pcw2T, g_cw2T);
    cudaGetSymbolAddress((void**)&pbw1T, g_bw1T);
    cudaGetSymbolAddress((void**)&pbw2T, g_bw2T);
    cudaGetSymbolAddress((void**)&pwcrT, g_wcrT);

    cudaFuncSetAttribute(mma_gemm<GEPI_GELU,  false>, cudaFuncAttributeMaxDynamicSharedMemorySize, MMA_SMEM_BYTES);
    cudaFuncSetAttribute(mma_gemm<GEPI_TANH,  false>, cudaFuncAttributeMaxDynamicSharedMemorySize, MMA_SMEM_BYTES);
    cudaFuncSetAttribute(mma_gemm<GEPI_BLOCK, false>, cudaFuncAttributeMaxDynamicSharedMemorySize, MMA_SMEM_BYTES);
    cudaFuncSetAttribute(mma_gemm<GEPI_BIAS,  true >, cudaFuncAttributeMaxDynamicSharedMemorySize, MMA_SMEM_BYTES);

    dim3 tb(32, 8);
    dim3 gN4(4, Msz / 128);
    dim3 gN8(8, Msz / 128);

    // ---- prologue on default stream: input copies + cross weights only ----
    cudaMemcpyAsync(pc, in_c, (size_t)BSD * 4, cudaMemcpyDeviceToDevice, 0);
    cudaMemcpyAsync(pb, in_b, (size_t)BSD * 4, cudaMemcpyDeviceToDevice, 0);
    transpose_h_kernel<<<dim3(16, 32, 1), tb>>>(wcr + (size_t)3 * 1024 * 512, pwcrT, 1024, 512, nullptr);
    cudaEventRecord(s_eF, 0);
    cudaStreamWaitEvent(s_sA, s_eF, 0);
    cudaStreamWaitEvent(s_sB, s_eF, 0);

    for (int l = 0; l < LNUM; l++) {
        int par = l & 1;
        float* mcl = pmc + (size_t)par * Bsz * Dsz;
        float* mbl = pmb + (size_t)par * Bsz * Dsz;

        // ---- stream A: cortical mean/route/transpose, record mean event ----
        colmean_kernel<<<dim3(Bsz, 2), 256, 0, s_sA>>>(pc, mcl);
        route_kernel<<<1, 256, 0, s_sA>>>(mcl, wsel_c + (size_t)l * Dsz * NB, bsel_c + l * NB, ptc);
        transpose_h_kernel<<<dim3(32, 16, 2), tb, 0, s_sA>>>(cw1 + (size_t)l * NB * 512 * 1024,
                                                             pcw1T + (size_t)l * NB * 1024 * 512, 512, 1024, ptc);
        transpose_h_kernel<<<dim3(16, 32, 2), tb, 0, s_sA>>>(cw2 + (size_t)l * NB * 1024 * 512,
                                                             pcw2T + (size_t)l * NB * 512 * 1024, 1024, 512, ptc);
        cudaEventRecord(s_eAm, s_sA);

        // ---- stream B: brainstem mean/route/transpose, record mean event ----
        colmean_kernel<<<dim3(Bsz, 2), 256, 0, s_sB>>>(pb, mbl);
        route_kernel<<<1, 256, 0, s_sB>>>(mbl, wsel_b + (size_t)l * Dsz * NB, bsel_b + l * NB, ptb);
        transpose_h_kernel<<<dim3(16, 16, 2), tb, 0, s_sB>>>(bw1 + (size_t)l * NB * 512 * 512,
                                                             pbw1T + (size_t)l * NB * 512 * 512, 512, 512, ptb);
        transpose_h_kernel<<<dim3(16, 16, 2), tb, 0, s_sB>>>(bw2 + (size_t)l * NB * 512 * 512,
                                                             pbw2T + (size_t)l * NB * 512 * 512, 512, 512, ptb);
        cudaEventRecord(s_eBm, s_sB);

        __half* cmir = (l == LNUM - 1) ? pcm : nullptr;
        __half* bmir = (l == LNUM - 1) ? pbm : nullptr;

        // ---- stream A: cortical blocks ----
        for (int j = 0; j < 2; j++) {
            ln_kernel<<<Msz / 8, 256, 0, s_sA>>>(pc, pxnc, clng + (size_t)l * NB * Dsz,
                                                 clnb + (size_t)l * NB * Dsz, ptc, j);
            mma_gemm<GEPI_GELU, false><<<gN8, 256, MMA_SMEM_BYTES, s_sA>>>(
                pxnc, nullptr, pcw1T + (size_t)l * NB * 1024 * 512,
                cb1 + (size_t)l * NB * 1024, ph1c, nullptr, Msz, 1024, 512,
                nullptr, nullptr, nullptr, ptc, j);
            if (j == 0) cudaStreamWaitEvent(s_sA, s_eBm, 0);   // need brainstem means
            mma_gemm<GEPI_BLOCK, false><<<gN4, 256, MMA_SMEM_BYTES, s_sA>>>(
                ph1c, nullptr, pcw2T + (size_t)l * NB * 512 * 1024,
                cb2 + (size_t)l * NB * 512, pc, cmir, Msz, 512, 1024,
                cg + (size_t)l * NB * Dsz, tors, mbl, ptc, j);
        }
        // ---- stream B: brainstem blocks ----
        for (int j = 0; j < 2; j++) {
            ln_kernel<<<Msz / 8, 256, 0, s_sB>>>(pb, pxnb, blng + (size_t)l * NB * Dsz,
                                                 blnb + (size_t)l * NB * Dsz, ptb, j);
            mma_gemm<GEPI_TANH, false><<<gN4, 256, MMA_SMEM_BYTES, s_sB>>>(
                pxnb, nullptr, pbw1T + (size_t)l * NB * 512 * 512,
                bb1 + (size_t)l * NB * 512, ph1b, nullptr, Msz, 512, 512,
                nullptr, nullptr, nullptr, ptb, j);
            if (j == 0) cudaStreamWaitEvent(s_sB, s_eAm, 0);   // need cortical means
            mma_gemm<GEPI_BLOCK, false><<<gN4, 256, MMA_SMEM_BYTES, s_sB>>>(
                ph1b, nullptr, pbw2T + (size_t)l * NB * 512 * 512,
                bb2 + (size_t)l * NB * 512, pb, bmir, Msz, 512, 512,
                bg + (size_t)l * NB * Dsz, tors, mcl, ptb, j);
        }
    }

    // final state copies (on own streams) + cross GEMM joined on default stream
    cudaMemcpyAsync(out,       pc, (size_t)BSD * 4, cudaMemcpyDeviceToDevice, s_sA);
    cudaMemcpyAsync(out + BSD, pb, (size_t)BSD * 4, cudaMemcpyDeviceToDevice, s_sB);
    cudaEventRecord(s_eAf, s_sA);
    cudaEventRecord(s_eBf, s_sB);
    cudaStreamWaitEvent(0, s_eAf, 0);
    cudaStreamWaitEvent(0, s_eBf, 0);
    mma_gemm<GEPI_BIAS, true><<<gN4, 256, MMA_SMEM_BYTES>>>(
        pcm, pbm, pwcrT, bcr + (size_t)3 * Dsz,
        out + 2 * (size_t)BSD, nullptr, Msz, 512, 1024,
        nullptr, nullptr, nullptr, nullptr, 0);
}